// round 1
// baseline (speedup 1.0000x reference)
#include <cuda_runtime.h>

#define NMAX 200000
#define EMAX 6400000
#define HD 128
#define INDIM 60

// ---------------- static device scratch (no allocations allowed) ------------
__device__ int g_cnt[NMAX];
__device__ int g_rowptr[NMAX + 1];
__device__ int g_cur[NMAX];
__device__ int g_cols[EMAX];
__device__ float g_vals[EMAX];
__device__ float g_neigh[(size_t)NMAX * HD];
__device__ float g_gsum[HD];
__device__ unsigned g_gmax[HD];

// ---------------- init: zero histogram + pool accumulators ------------------
__global__ void k_init(int n) {
    int i = blockIdx.x * blockDim.x + threadIdx.x;
    if (i < n) g_cnt[i] = 0;
    if (i < HD) { g_gsum[i] = 0.f; g_gmax[i] = 0u; }
}

// ---------------- CSR build: histogram -> scan -> reorder -------------------
__global__ void k_hist(const int* __restrict__ er, int e) {
    int i = blockIdx.x * blockDim.x + threadIdx.x;
    if (i < e) atomicAdd(&g_cnt[er[i]], 1);
}

__global__ void k_scan(int n) {
    __shared__ int s[1024];
    int tid = threadIdx.x;
    int ch = (n + 1023) >> 10;
    int st = tid * ch;
    int en = min(st + ch, n);
    int sum = 0;
    for (int i = st; i < en; i++) sum += g_cnt[i];
    s[tid] = sum;
    __syncthreads();
    for (int off = 1; off < 1024; off <<= 1) {
        int v = (tid >= off) ? s[tid - off] : 0;
        __syncthreads();
        s[tid] += v;
        __syncthreads();
    }
    int pre = (tid == 0) ? 0 : s[tid - 1];
    for (int i = st; i < en; i++) {
        g_rowptr[i] = pre;
        g_cur[i] = pre;
        pre += g_cnt[i];
    }
    if (tid == 0) g_rowptr[n] = s[1023];
}

__global__ void k_reorder(const int* __restrict__ er, const int* __restrict__ ec,
                          const float* __restrict__ ev, int e) {
    int i = blockIdx.x * blockDim.x + threadIdx.x;
    if (i < e) {
        int r = er[i];
        int p = atomicAdd(&g_cur[r], 1);
        g_cols[p] = ec[i];
        g_vals[p] = ev[i];
    }
}

// ---------------- fused embedding-gather + 2-layer input MLP ----------------
// smem: W1(60x128) W2(128x128) b1 b2 x(128x60) h1(128x128)
#define SMEM_MLP ((60 * 128 + 128 * 128 + 128 + 128 + 128 * 60 + 128 * 128) * 4)

__global__ void __launch_bounds__(512, 1) k_input_mlp(
    const int* __restrict__ mi, const int* __restrict__ wi, const int* __restrict__ ti,
    const float* __restrict__ cont,
    const float* __restrict__ memb, const float* __restrict__ wemb, const float* __restrict__ temb,
    const float* __restrict__ W1, const float* __restrict__ b1,
    const float* __restrict__ W2, const float* __restrict__ b2,
    float* __restrict__ hout, int n)
{
    extern __shared__ float sm[];
    float* sW1 = sm;                       // 7680
    float* sW2 = sW1 + 60 * 128;           // 16384
    float* sb1 = sW2 + 128 * 128;          // 128
    float* sb2 = sb1 + 128;                // 128
    float* sx  = sb2 + 128;                // 7680
    float* sh1 = sx + 128 * 60;            // 16384

    int tid = threadIdx.x;
    for (int i = tid; i < 60 * 128; i += 512) sW1[i] = W1[i];
    for (int i = tid; i < 128 * 128; i += 512) sW2[i] = W2[i];
    if (tid < 128) { sb1[tid] = b1[tid]; sb2[tid] = b2[tid]; }

    int base = blockIdx.x * 128;
    // gather x tile [128 nodes x 60 features]
    for (int i = tid; i < 128 * 60; i += 512) {
        int nd = i / 60, f = i - nd * 60;
        int node = base + nd;
        float v = 0.f;
        if (node < n) {
            if (f < 16)       v = memb[mi[node] * 16 + f];
            else if (f < 32)  v = wemb[wi[node] * 16 + (f - 16)];
            else if (f < 48)  v = temb[ti[node] * 16 + (f - 32)];
            else              v = cont[(size_t)node * 12 + (f - 48)];
        }
        sx[i] = v;
    }
    __syncthreads();

    int c0 = (tid & 31) * 4;
    int r0 = (tid >> 5) * 8;

    // GEMM1: h1 = relu(x @ W1 + b1)
    float acc[8][4];
    #pragma unroll
    for (int r = 0; r < 8; r++)
        #pragma unroll
        for (int c = 0; c < 4; c++) acc[r][c] = 0.f;

    #pragma unroll 4
    for (int k = 0; k < 60; k++) {
        float4 w = *(float4*)&sW1[k * 128 + c0];
        #pragma unroll
        for (int r = 0; r < 8; r++) {
            float a = sx[(r0 + r) * 60 + k];
            acc[r][0] += a * w.x; acc[r][1] += a * w.y;
            acc[r][2] += a * w.z; acc[r][3] += a * w.w;
        }
    }
    {
        float4 bb = *(float4*)&sb1[c0];
        #pragma unroll
        for (int r = 0; r < 8; r++) {
            float4 o;
            o.x = fmaxf(acc[r][0] + bb.x, 0.f);
            o.y = fmaxf(acc[r][1] + bb.y, 0.f);
            o.z = fmaxf(acc[r][2] + bb.z, 0.f);
            o.w = fmaxf(acc[r][3] + bb.w, 0.f);
            *(float4*)&sh1[(r0 + r) * 128 + c0] = o;
        }
    }
    __syncthreads();

    // GEMM2: h = relu(h1 @ W2 + b2)
    #pragma unroll
    for (int r = 0; r < 8; r++)
        #pragma unroll
        for (int c = 0; c < 4; c++) acc[r][c] = 0.f;

    #pragma unroll 4
    for (int k = 0; k < 128; k++) {
        float4 w = *(float4*)&sW2[k * 128 + c0];
        #pragma unroll
        for (int r = 0; r < 8; r++) {
            float a = sh1[(r0 + r) * 128 + k];
            acc[r][0] += a * w.x; acc[r][1] += a * w.y;
            acc[r][2] += a * w.z; acc[r][3] += a * w.w;
        }
    }
    {
        float4 bb = *(float4*)&sb2[c0];
        #pragma unroll
        for (int r = 0; r < 8; r++) {
            int node = base + r0 + r;
            if (node < n) {
                float4 o;
                o.x = fmaxf(acc[r][0] + bb.x, 0.f);
                o.y = fmaxf(acc[r][1] + bb.y, 0.f);
                o.z = fmaxf(acc[r][2] + bb.z, 0.f);
                o.w = fmaxf(acc[r][3] + bb.w, 0.f);
                *(float4*)&hout[(size_t)node * 128 + c0] = o;
            }
        }
    }
}

// ---------------- SpMM: warp per row, register accumulation -----------------
__global__ void k_spmm(const float* __restrict__ h, int n) {
    int row = (blockIdx.x * blockDim.x + threadIdx.x) >> 5;
    if (row >= n) return;
    int lane = threadIdx.x & 31;
    int beg = g_rowptr[row], end = g_rowptr[row + 1];
    float4 acc = {0.f, 0.f, 0.f, 0.f};
    int e = beg;
    for (; e + 1 < end; e += 2) {
        int c0 = g_cols[e];     float v0 = g_vals[e];
        int c1 = g_cols[e + 1]; float v1 = g_vals[e + 1];
        float4 x0 = *(const float4*)&h[(size_t)c0 * 128 + lane * 4];
        float4 x1 = *(const float4*)&h[(size_t)c1 * 128 + lane * 4];
        acc.x += v0 * x0.x; acc.y += v0 * x0.y; acc.z += v0 * x0.z; acc.w += v0 * x0.w;
        acc.x += v1 * x1.x; acc.y += v1 * x1.y; acc.z += v1 * x1.z; acc.w += v1 * x1.w;
    }
    if (e < end) {
        int c = g_cols[e]; float v = g_vals[e];
        float4 x = *(const float4*)&h[(size_t)c * 128 + lane * 4];
        acc.x += v * x.x; acc.y += v * x.y; acc.z += v * x.z; acc.w += v * x.w;
    }
    *(float4*)&g_neigh[(size_t)row * 128 + lane * 4] = acc;
}

// ---------------- layer update: h += relu(h@Ws + neigh@Wn + bs + bn) --------
#define SMEM_LAYER ((2 * 128 * 128 + 2 * 128 * 32) * 4)

__global__ void __launch_bounds__(512, 1) k_layer(
    const float* __restrict__ Ws, const float* __restrict__ bs,
    const float* __restrict__ Wn, const float* __restrict__ bn,
    float* __restrict__ h, int n)
{
    extern __shared__ float sm[];
    float* sWs = sm;                       // 16384
    float* sWn = sWs + 128 * 128;          // 16384
    float* sA  = sWn + 128 * 128;          // 4096
    float* sB  = sA + 128 * 32;            // 4096

    int tid = threadIdx.x;
    for (int i = tid; i < 128 * 128; i += 512) { sWs[i] = Ws[i]; sWn[i] = Wn[i]; }

    int base = blockIdx.x * 128;
    int c0 = (tid & 31) * 4;
    int r0 = (tid >> 5) * 8;

    float acc[8][4];
    #pragma unroll
    for (int r = 0; r < 8; r++)
        #pragma unroll
        for (int c = 0; c < 4; c++) acc[r][c] = 0.f;

    for (int kc = 0; kc < 4; kc++) {
        __syncthreads();
        for (int i = tid; i < 128 * 32; i += 512) {
            int nd = i >> 5, k = i & 31;
            int node = base + nd;
            float a = 0.f, b = 0.f;
            if (node < n) {
                size_t off = (size_t)node * 128 + kc * 32 + k;
                a = h[off];
                b = g_neigh[off];
            }
            sA[i] = a; sB[i] = b;
        }
        __syncthreads();
        #pragma unroll 4
        for (int kk = 0; kk < 32; kk++) {
            int k = kc * 32 + kk;
            float4 ws = *(float4*)&sWs[k * 128 + c0];
            float4 wn = *(float4*)&sWn[k * 128 + c0];
            #pragma unroll
            for (int r = 0; r < 8; r++) {
                float a = sA[(r0 + r) * 32 + kk];
                float b = sB[(r0 + r) * 32 + kk];
                acc[r][0] += a * ws.x + b * wn.x;
                acc[r][1] += a * ws.y + b * wn.y;
                acc[r][2] += a * ws.z + b * wn.z;
                acc[r][3] += a * ws.w + b * wn.w;
            }
        }
    }

    float4 vbs = *(float4*)&bs[c0];
    float4 vbn = *(float4*)&bn[c0];
    #pragma unroll
    for (int r = 0; r < 8; r++) {
        int node = base + r0 + r;
        if (node < n) {
            float4* hp = (float4*)&h[(size_t)node * 128 + c0];
            float4 hv = *hp;
            hv.x += fmaxf(acc[r][0] + vbs.x + vbn.x, 0.f);
            hv.y += fmaxf(acc[r][1] + vbs.y + vbn.y, 0.f);
            hv.z += fmaxf(acc[r][2] + vbs.z + vbn.z, 0.f);
            hv.w += fmaxf(acc[r][3] + vbs.w + vbn.w, 0.f);
            *hp = hv;
        }
    }
}

// ---------------- global mean/max pool --------------------------------------
// h >= 0 always (relu chain + nonneg residual), so uint atomicMax is valid.
__global__ void k_reduce(const float* __restrict__ h, int n) {
    int t = threadIdx.x;  // 128
    float s = 0.f, m = 0.f;
    for (int node = blockIdx.x; node < n; node += gridDim.x) {
        float v = h[(size_t)node * 128 + t];
        s += v;
        m = fmaxf(m, v);
    }
    atomicAdd(&g_gsum[t], s);
    atomicMax(&g_gmax[t], __float_as_uint(m));
}

__global__ void k_final(float* __restrict__ out, int n) {
    int t = threadIdx.x;  // 256
    if (t < 128) out[t] = g_gsum[t] / (float)n;
    else out[t] = __uint_as_float(g_gmax[t - 128]);
}

// ---------------- launch -----------------------------------------------------
extern "C" void kernel_launch(void* const* d_in, const int* in_sizes, int n_in,
                              void* d_out, int out_size) {
    const int*   mi   = (const int*)d_in[0];
    const int*   wi   = (const int*)d_in[1];
    const int*   ti   = (const int*)d_in[2];
    const float* cont = (const float*)d_in[3];
    const int*   er   = (const int*)d_in[4];
    const int*   ec   = (const int*)d_in[5];
    const float* ev   = (const float*)d_in[6];
    const float* memb = (const float*)d_in[7];
    const float* wemb = (const float*)d_in[8];
    const float* temb = (const float*)d_in[9];
    const float* W1   = (const float*)d_in[10];
    const float* b1   = (const float*)d_in[11];
    const float* W2   = (const float*)d_in[12];
    const float* b2   = (const float*)d_in[13];
    const float* Wself  = (const float*)d_in[14];
    const float* bself  = (const float*)d_in[15];
    const float* Wneigh = (const float*)d_in[16];
    const float* bneigh = (const float*)d_in[17];

    int n = in_sizes[0];
    int e = in_sizes[4];

    float* out = (float*)d_out;
    float* h = out + 256;

    cudaFuncSetAttribute(k_input_mlp, cudaFuncAttributeMaxDynamicSharedMemorySize, SMEM_MLP);
    cudaFuncSetAttribute(k_layer, cudaFuncAttributeMaxDynamicSharedMemorySize, SMEM_LAYER);

    int ntile = (n + 127) / 128;

    k_init<<<(n + 255) / 256, 256>>>(n);
    k_hist<<<(e + 255) / 256, 256>>>(er, e);
    k_scan<<<1, 1024>>>(n);
    k_reorder<<<(e + 255) / 256, 256>>>(er, ec, ev, e);

    k_input_mlp<<<ntile, 512, SMEM_MLP>>>(mi, wi, ti, cont, memb, wemb, temb,
                                          W1, b1, W2, b2, h, n);

    for (int l = 0; l < 2; l++) {
        int nwarp_blocks = (int)(((long long)n * 32 + 255) / 256);
        k_spmm<<<nwarp_blocks, 256>>>(h, n);
        k_layer<<<ntile, 512, SMEM_LAYER>>>(Wself + (size_t)l * 128 * 128, bself + l * 128,
                                            Wneigh + (size_t)l * 128 * 128, bneigh + l * 128,
                                            h, n);
    }

    k_reduce<<<1024, 128>>>(h, n);
    k_final<<<1, 256>>>(out, n);
}

// round 2
// speedup vs baseline: 1.0622x; 1.0622x over previous
#include <cuda_runtime.h>

#define NMAX 200000
#define EMAX 6400000
#define HD 128

typedef unsigned long long u64;

// ---------------- f32x2 packed-FMA helpers (Blackwell FFMA2 via PTX) --------
__device__ __forceinline__ u64 pack2(float a, float b) {
    u64 r;
    asm("mov.b64 %0, {%1, %2};" : "=l"(r) : "f"(a), "f"(b));
    return r;
}
__device__ __forceinline__ void fma2(u64& d, u64 a, u64 b) {
    asm("fma.rn.f32x2 %0, %1, %2, %0;" : "+l"(d) : "l"(a), "l"(b));
}
__device__ __forceinline__ float2 unpack2(u64 v) {
    float2 f;
    asm("mov.b64 {%0, %1}, %2;" : "=f"(f.x), "=f"(f.y) : "l"(v));
    return f;
}

// ---------------- static device scratch (no allocations allowed) ------------
__device__ int g_cnt[NMAX];
__device__ int g_rowptr[NMAX + 1];
__device__ int g_cur[NMAX];
__device__ uint2 g_edges[EMAX];          // (col, val-bits) packed 8B
__device__ float g_neigh[(size_t)NMAX * HD];
__device__ float g_gsum[HD];
__device__ unsigned g_gmax[HD];

// ---------------- init: zero histogram + pool accumulators ------------------
__global__ void k_init(int n) {
    int i = blockIdx.x * blockDim.x + threadIdx.x;
    if (i < n) g_cnt[i] = 0;
    if (i < HD) { g_gsum[i] = 0.f; g_gmax[i] = 0u; }
}

// ---------------- CSR build: histogram -> scan -> reorder -------------------
__global__ void k_hist(const int* __restrict__ er, int e) {
    int i = blockIdx.x * blockDim.x + threadIdx.x;
    if (i < e) atomicAdd(&g_cnt[er[i]], 1);
}

__global__ void k_scan(int n) {
    __shared__ int s[1024];
    int tid = threadIdx.x;
    int ch = (n + 1023) >> 10;
    int st = tid * ch;
    int en = min(st + ch, n);
    int sum = 0;
    for (int i = st; i < en; i++) sum += g_cnt[i];
    s[tid] = sum;
    __syncthreads();
    for (int off = 1; off < 1024; off <<= 1) {
        int v = (tid >= off) ? s[tid - off] : 0;
        __syncthreads();
        s[tid] += v;
        __syncthreads();
    }
    int pre = (tid == 0) ? 0 : s[tid - 1];
    for (int i = st; i < en; i++) {
        g_rowptr[i] = pre;
        g_cur[i] = pre;
        pre += g_cnt[i];
    }
    if (tid == 0) g_rowptr[n] = s[1023];
}

__global__ void k_reorder(const int* __restrict__ er, const int* __restrict__ ec,
                          const float* __restrict__ ev, int e) {
    int i = blockIdx.x * blockDim.x + threadIdx.x;
    if (i < e) {
        int r = er[i];
        int p = atomicAdd(&g_cur[r], 1);
        uint2 pk;
        pk.x = (unsigned)ec[i];
        pk.y = __float_as_uint(ev[i]);
        g_edges[p] = pk;
    }
}

// ---------------- fused embedding-gather + 2-layer input MLP ----------------
// smem: W1(60x128) W2(128x128) b1 b2 x(128x60) h1(128x128)
#define SMEM_MLP ((60 * 128 + 128 * 128 + 128 + 128 + 128 * 60 + 128 * 128) * 4)

__global__ void __launch_bounds__(512, 1) k_input_mlp(
    const int* __restrict__ mi, const int* __restrict__ wi, const int* __restrict__ ti,
    const float* __restrict__ cont,
    const float* __restrict__ memb, const float* __restrict__ wemb, const float* __restrict__ temb,
    const float* __restrict__ W1, const float* __restrict__ b1,
    const float* __restrict__ W2, const float* __restrict__ b2,
    float* __restrict__ hout, int n)
{
    extern __shared__ float sm[];
    float* sW1 = sm;                       // 7680
    float* sW2 = sW1 + 60 * 128;           // 16384
    float* sb1 = sW2 + 128 * 128;          // 128
    float* sb2 = sb1 + 128;                // 128
    float* sx  = sb2 + 128;                // 7680
    float* sh1 = sx + 128 * 60;            // 16384

    int tid = threadIdx.x;
    for (int i = tid; i < 60 * 128; i += 512) sW1[i] = W1[i];
    for (int i = tid; i < 128 * 128; i += 512) sW2[i] = W2[i];
    if (tid < 128) { sb1[tid] = b1[tid]; sb2[tid] = b2[tid]; }

    int base = blockIdx.x * 128;
    // gather x tile [128 nodes x 60 features]
    for (int i = tid; i < 128 * 60; i += 512) {
        int nd = i / 60, f = i - nd * 60;
        int node = base + nd;
        float v = 0.f;
        if (node < n) {
            if (f < 16)       v = memb[mi[node] * 16 + f];
            else if (f < 32)  v = wemb[wi[node] * 16 + (f - 16)];
            else if (f < 48)  v = temb[ti[node] * 16 + (f - 32)];
            else              v = cont[(size_t)node * 12 + (f - 48)];
        }
        sx[i] = v;
    }
    __syncthreads();

    int c0 = (tid & 31) * 4;
    int r0 = (tid >> 5) * 8;

    // GEMM1: h1 = relu(x @ W1 + b1)   (packed f32x2)
    u64 acc01[8], acc23[8];
    #pragma unroll
    for (int r = 0; r < 8; r++) { acc01[r] = 0ull; acc23[r] = 0ull; }

    #pragma unroll 4
    for (int k = 0; k < 60; k++) {
        ulonglong2 w = *(ulonglong2*)&sW1[k * 128 + c0];
        #pragma unroll
        for (int r = 0; r < 8; r++) {
            float a = sx[(r0 + r) * 60 + k];
            u64 a2 = pack2(a, a);
            fma2(acc01[r], a2, w.x);
            fma2(acc23[r], a2, w.y);
        }
    }
    {
        float4 bb = *(float4*)&sb1[c0];
        #pragma unroll
        for (int r = 0; r < 8; r++) {
            float2 v01 = unpack2(acc01[r]);
            float2 v23 = unpack2(acc23[r]);
            float4 o;
            o.x = fmaxf(v01.x + bb.x, 0.f);
            o.y = fmaxf(v01.y + bb.y, 0.f);
            o.z = fmaxf(v23.x + bb.z, 0.f);
            o.w = fmaxf(v23.y + bb.w, 0.f);
            *(float4*)&sh1[(r0 + r) * 128 + c0] = o;
        }
    }
    __syncthreads();

    // GEMM2: h = relu(h1 @ W2 + b2)   (packed f32x2)
    #pragma unroll
    for (int r = 0; r < 8; r++) { acc01[r] = 0ull; acc23[r] = 0ull; }

    #pragma unroll 4
    for (int k = 0; k < 128; k++) {
        ulonglong2 w = *(ulonglong2*)&sW2[k * 128 + c0];
        #pragma unroll
        for (int r = 0; r < 8; r++) {
            float a = sh1[(r0 + r) * 128 + k];
            u64 a2 = pack2(a, a);
            fma2(acc01[r], a2, w.x);
            fma2(acc23[r], a2, w.y);
        }
    }
    {
        float4 bb = *(float4*)&sb2[c0];
        #pragma unroll
        for (int r = 0; r < 8; r++) {
            int node = base + r0 + r;
            if (node < n) {
                float2 v01 = unpack2(acc01[r]);
                float2 v23 = unpack2(acc23[r]);
                float4 o;
                o.x = fmaxf(v01.x + bb.x, 0.f);
                o.y = fmaxf(v01.y + bb.y, 0.f);
                o.z = fmaxf(v23.x + bb.z, 0.f);
                o.w = fmaxf(v23.y + bb.w, 0.f);
                *(float4*)&hout[(size_t)node * 128 + c0] = o;
            }
        }
    }
}

// ---------------- SpMM: warp per row, register accumulation -----------------
__global__ void k_spmm(const float* __restrict__ h, int n) {
    int row = (blockIdx.x * blockDim.x + threadIdx.x) >> 5;
    if (row >= n) return;
    int lane = threadIdx.x & 31;
    int beg = g_rowptr[row], end = g_rowptr[row + 1];
    float4 acc = {0.f, 0.f, 0.f, 0.f};
    int e = beg;
    for (; e + 1 < end; e += 2) {
        uint2 e0 = g_edges[e];
        uint2 e1 = g_edges[e + 1];
        float v0 = __uint_as_float(e0.y);
        float v1 = __uint_as_float(e1.y);
        float4 x0 = *(const float4*)&h[(size_t)e0.x * 128 + lane * 4];
        float4 x1 = *(const float4*)&h[(size_t)e1.x * 128 + lane * 4];
        acc.x += v0 * x0.x; acc.y += v0 * x0.y; acc.z += v0 * x0.z; acc.w += v0 * x0.w;
        acc.x += v1 * x1.x; acc.y += v1 * x1.y; acc.z += v1 * x1.z; acc.w += v1 * x1.w;
    }
    if (e < end) {
        uint2 e0 = g_edges[e];
        float v = __uint_as_float(e0.y);
        float4 x = *(const float4*)&h[(size_t)e0.x * 128 + lane * 4];
        acc.x += v * x.x; acc.y += v * x.y; acc.z += v * x.z; acc.w += v * x.w;
    }
    *(float4*)&g_neigh[(size_t)row * 128 + lane * 4] = acc;
}

// ---------------- layer update: h += relu(h@Ws + neigh@Wn + bs + bn) --------
#define SMEM_LAYER ((2 * 128 * 128 + 2 * 128 * 32) * 4)

__global__ void __launch_bounds__(512, 1) k_layer(
    const float* __restrict__ Ws, const float* __restrict__ bs,
    const float* __restrict__ Wn, const float* __restrict__ bn,
    float* __restrict__ h, int n)
{
    extern __shared__ float sm[];
    float* sWs = sm;                       // 16384
    float* sWn = sWs + 128 * 128;          // 16384
    float* sA  = sWn + 128 * 128;          // 4096
    float* sB  = sA + 128 * 32;            // 4096

    int tid = threadIdx.x;
    for (int i = tid; i < 128 * 128; i += 512) { sWs[i] = Ws[i]; sWn[i] = Wn[i]; }

    int base = blockIdx.x * 128;
    int c0 = (tid & 31) * 4;
    int r0 = (tid >> 5) * 8;

    u64 acc01[8], acc23[8];
    #pragma unroll
    for (int r = 0; r < 8; r++) { acc01[r] = 0ull; acc23[r] = 0ull; }

    for (int kc = 0; kc < 4; kc++) {
        __syncthreads();
        for (int i = tid; i < 128 * 32; i += 512) {
            int nd = i >> 5, k = i & 31;
            int node = base + nd;
            float a = 0.f, b = 0.f;
            if (node < n) {
                size_t off = (size_t)node * 128 + kc * 32 + k;
                a = h[off];
                b = g_neigh[off];
            }
            sA[i] = a; sB[i] = b;
        }
        __syncthreads();
        #pragma unroll 4
        for (int kk = 0; kk < 32; kk++) {
            int k = kc * 32 + kk;
            ulonglong2 ws = *(ulonglong2*)&sWs[k * 128 + c0];
            ulonglong2 wn = *(ulonglong2*)&sWn[k * 128 + c0];
            #pragma unroll
            for (int r = 0; r < 8; r++) {
                float a = sA[(r0 + r) * 32 + kk];
                float b = sB[(r0 + r) * 32 + kk];
                u64 a2 = pack2(a, a);
                u64 b2 = pack2(b, b);
                fma2(acc01[r], a2, ws.x);
                fma2(acc23[r], a2, ws.y);
                fma2(acc01[r], b2, wn.x);
                fma2(acc23[r], b2, wn.y);
            }
        }
    }

    float4 vbs = *(float4*)&bs[c0];
    float4 vbn = *(float4*)&bn[c0];
    float bx = vbs.x + vbn.x, by = vbs.y + vbn.y;
    float bz = vbs.z + vbn.z, bw = vbs.w + vbn.w;
    #pragma unroll
    for (int r = 0; r < 8; r++) {
        int node = base + r0 + r;
        if (node < n) {
            float4* hp = (float4*)&h[(size_t)node * 128 + c0];
            float4 hv = *hp;
            float2 v01 = unpack2(acc01[r]);
            float2 v23 = unpack2(acc23[r]);
            hv.x += fmaxf(v01.x + bx, 0.f);
            hv.y += fmaxf(v01.y + by, 0.f);
            hv.z += fmaxf(v23.x + bz, 0.f);
            hv.w += fmaxf(v23.y + bw, 0.f);
            *hp = hv;
        }
    }
}

// ---------------- global mean/max pool --------------------------------------
// h >= 0 always (relu chain + nonneg residual), so uint atomicMax is valid.
__global__ void k_reduce(const float* __restrict__ h, int n) {
    int t = threadIdx.x;  // 128
    float s = 0.f, m = 0.f;
    for (int node = blockIdx.x; node < n; node += gridDim.x) {
        float v = h[(size_t)node * 128 + t];
        s += v;
        m = fmaxf(m, v);
    }
    atomicAdd(&g_gsum[t], s);
    atomicMax(&g_gmax[t], __float_as_uint(m));
}

__global__ void k_final(float* __restrict__ out, int n) {
    int t = threadIdx.x;  // 256
    if (t < 128) out[t] = g_gsum[t] / (float)n;
    else out[t] = __uint_as_float(g_gmax[t - 128]);
}

// ---------------- launch -----------------------------------------------------
extern "C" void kernel_launch(void* const* d_in, const int* in_sizes, int n_in,
                              void* d_out, int out_size) {
    const int*   mi   = (const int*)d_in[0];
    const int*   wi   = (const int*)d_in[1];
    const int*   ti   = (const int*)d_in[2];
    const float* cont = (const float*)d_in[3];
    const int*   er   = (const int*)d_in[4];
    const int*   ec   = (const int*)d_in[5];
    const float* ev   = (const float*)d_in[6];
    const float* memb = (const float*)d_in[7];
    const float* wemb = (const float*)d_in[8];
    const float* temb = (const float*)d_in[9];
    const float* W1   = (const float*)d_in[10];
    const float* b1   = (const float*)d_in[11];
    const float* W2   = (const float*)d_in[12];
    const float* b2   = (const float*)d_in[13];
    const float* Wself  = (const float*)d_in[14];
    const float* bself  = (const float*)d_in[15];
    const float* Wneigh = (const float*)d_in[16];
    const float* bneigh = (const float*)d_in[17];

    int n = in_sizes[0];
    int e = in_sizes[4];

    float* out = (float*)d_out;
    float* h = out + 256;

    cudaFuncSetAttribute(k_input_mlp, cudaFuncAttributeMaxDynamicSharedMemorySize, SMEM_MLP);
    cudaFuncSetAttribute(k_layer, cudaFuncAttributeMaxDynamicSharedMemorySize, SMEM_LAYER);

    int ntile = (n + 127) / 128;

    k_init<<<(n + 255) / 256, 256>>>(n);
    k_hist<<<(e + 255) / 256, 256>>>(er, e);
    k_scan<<<1, 1024>>>(n);
    k_reorder<<<(e + 255) / 256, 256>>>(er, ec, ev, e);

    k_input_mlp<<<ntile, 512, SMEM_MLP>>>(mi, wi, ti, cont, memb, wemb, temb,
                                          W1, b1, W2, b2, h, n);

    for (int l = 0; l < 2; l++) {
        int nwarp_blocks = (int)(((long long)n * 32 + 255) / 256);
        k_spmm<<<nwarp_blocks, 256>>>(h, n);
        k_layer<<<ntile, 512, SMEM_LAYER>>>(Wself + (size_t)l * 128 * 128, bself + l * 128,
                                            Wneigh + (size_t)l * 128 * 128, bneigh + l * 128,
                                            h, n);
    }

    k_reduce<<<1024, 128>>>(h, n);
    k_final<<<1, 256>>>(out, n);
}

// round 3
// speedup vs baseline: 1.1740x; 1.1053x over previous
#include <cuda_runtime.h>
#include <cuda_fp16.h>

#define NMAX 200000
#define EMAX 6400000
#define HD 128

typedef unsigned long long u64;

// ---------------- f32x2 packed-FMA helpers (Blackwell FFMA2 via PTX) --------
__device__ __forceinline__ u64 pack2(float a, float b) {
    u64 r;
    asm("mov.b64 %0, {%1, %2};" : "=l"(r) : "f"(a), "f"(b));
    return r;
}
__device__ __forceinline__ void fma2(u64& d, u64 a, u64 b) {
    asm("fma.rn.f32x2 %0, %1, %2, %0;" : "+l"(d) : "l"(a), "l"(b));
}
__device__ __forceinline__ float2 unpack2(u64 v) {
    float2 f;
    asm("mov.b64 {%0, %1}, %2;" : "=f"(f.x), "=f"(f.y) : "l"(v));
    return f;
}

// ---------------- static device scratch (no allocations allowed) ------------
__device__ int g_cnt[NMAX];
__device__ int g_rowptr[NMAX + 1];
__device__ int g_cur[NMAX];
__device__ uint2 g_edges[EMAX];                 // (col, val-bits) packed 8B
__device__ float g_neigh[(size_t)NMAX * HD];
__device__ __half g_hb[(size_t)NMAX * HD];      // fp16 shadow of h for gathers
__device__ float g_gsum[HD];
__device__ unsigned g_gmax[HD];

// ---------------- init: zero histogram + pool accumulators ------------------
__global__ void k_init(int n) {
    int i = blockIdx.x * blockDim.x + threadIdx.x;
    if (i < n) g_cnt[i] = 0;
    if (i < HD) { g_gsum[i] = 0.f; g_gmax[i] = 0u; }
}

// ---------------- CSR build: histogram -> scan -> reorder -------------------
__global__ void k_hist(const int* __restrict__ er, int e) {
    int i = blockIdx.x * blockDim.x + threadIdx.x;
    if (i < e) atomicAdd(&g_cnt[er[i]], 1);
}

__global__ void k_scan(int n) {
    __shared__ int s[1024];
    int tid = threadIdx.x;
    int ch = (n + 1023) >> 10;
    int st = tid * ch;
    int en = min(st + ch, n);
    int sum = 0;
    for (int i = st; i < en; i++) sum += g_cnt[i];
    s[tid] = sum;
    __syncthreads();
    for (int off = 1; off < 1024; off <<= 1) {
        int v = (tid >= off) ? s[tid - off] : 0;
        __syncthreads();
        s[tid] += v;
        __syncthreads();
    }
    int pre = (tid == 0) ? 0 : s[tid - 1];
    for (int i = st; i < en; i++) {
        g_rowptr[i] = pre;
        g_cur[i] = pre;
        pre += g_cnt[i];
    }
    if (tid == 0) g_rowptr[n] = s[1023];
}

__global__ void k_reorder(const int* __restrict__ er, const int* __restrict__ ec,
                          const float* __restrict__ ev, int e) {
    int i = blockIdx.x * blockDim.x + threadIdx.x;
    if (i < e) {
        int r = er[i];
        int p = atomicAdd(&g_cur[r], 1);
        uint2 pk;
        pk.x = (unsigned)ec[i];
        pk.y = __float_as_uint(ev[i]);
        g_edges[p] = pk;
    }
}

// ---------------- store helper: fp32 float4 -> fp16x4 (8B) ------------------
__device__ __forceinline__ void store_hb(size_t off4, float4 o) {
    __half2 p0 = __floats2half2_rn(o.x, o.y);
    __half2 p1 = __floats2half2_rn(o.z, o.w);
    uint2 pk;
    pk.x = *(unsigned*)&p0;
    pk.y = *(unsigned*)&p1;
    *(uint2*)&g_hb[off4] = pk;
}

// ---------------- fused embedding-gather + 2-layer input MLP ----------------
#define SMEM_MLP ((60 * 128 + 128 * 128 + 128 + 128 + 128 * 60 + 128 * 128) * 4)

__global__ void __launch_bounds__(512, 1) k_input_mlp(
    const int* __restrict__ mi, const int* __restrict__ wi, const int* __restrict__ ti,
    const float* __restrict__ cont,
    const float* __restrict__ memb, const float* __restrict__ wemb, const float* __restrict__ temb,
    const float* __restrict__ W1, const float* __restrict__ b1,
    const float* __restrict__ W2, const float* __restrict__ b2,
    float* __restrict__ hout, int n)
{
    extern __shared__ float sm[];
    float* sW1 = sm;
    float* sW2 = sW1 + 60 * 128;
    float* sb1 = sW2 + 128 * 128;
    float* sb2 = sb1 + 128;
    float* sx  = sb2 + 128;
    float* sh1 = sx + 128 * 60;

    int tid = threadIdx.x;
    for (int i = tid; i < 60 * 128; i += 512) sW1[i] = W1[i];
    for (int i = tid; i < 128 * 128; i += 512) sW2[i] = W2[i];
    if (tid < 128) { sb1[tid] = b1[tid]; sb2[tid] = b2[tid]; }

    int base = blockIdx.x * 128;
    for (int i = tid; i < 128 * 60; i += 512) {
        int nd = i / 60, f = i - nd * 60;
        int node = base + nd;
        float v = 0.f;
        if (node < n) {
            if (f < 16)       v = memb[mi[node] * 16 + f];
            else if (f < 32)  v = wemb[wi[node] * 16 + (f - 16)];
            else if (f < 48)  v = temb[ti[node] * 16 + (f - 32)];
            else              v = cont[(size_t)node * 12 + (f - 48)];
        }
        sx[i] = v;
    }
    __syncthreads();

    int c0 = (tid & 31) * 4;
    int r0 = (tid >> 5) * 8;

    u64 acc01[8], acc23[8];
    #pragma unroll
    for (int r = 0; r < 8; r++) { acc01[r] = 0ull; acc23[r] = 0ull; }

    #pragma unroll 4
    for (int k = 0; k < 60; k++) {
        ulonglong2 w = *(ulonglong2*)&sW1[k * 128 + c0];
        #pragma unroll
        for (int r = 0; r < 8; r++) {
            float a = sx[(r0 + r) * 60 + k];
            u64 a2 = pack2(a, a);
            fma2(acc01[r], a2, w.x);
            fma2(acc23[r], a2, w.y);
        }
    }
    {
        float4 bb = *(float4*)&sb1[c0];
        #pragma unroll
        for (int r = 0; r < 8; r++) {
            float2 v01 = unpack2(acc01[r]);
            float2 v23 = unpack2(acc23[r]);
            float4 o;
            o.x = fmaxf(v01.x + bb.x, 0.f);
            o.y = fmaxf(v01.y + bb.y, 0.f);
            o.z = fmaxf(v23.x + bb.z, 0.f);
            o.w = fmaxf(v23.y + bb.w, 0.f);
            *(float4*)&sh1[(r0 + r) * 128 + c0] = o;
        }
    }
    __syncthreads();

    #pragma unroll
    for (int r = 0; r < 8; r++) { acc01[r] = 0ull; acc23[r] = 0ull; }

    #pragma unroll 4
    for (int k = 0; k < 128; k++) {
        ulonglong2 w = *(ulonglong2*)&sW2[k * 128 + c0];
        #pragma unroll
        for (int r = 0; r < 8; r++) {
            float a = sh1[(r0 + r) * 128 + k];
            u64 a2 = pack2(a, a);
            fma2(acc01[r], a2, w.x);
            fma2(acc23[r], a2, w.y);
        }
    }
    {
        float4 bb = *(float4*)&sb2[c0];
        #pragma unroll
        for (int r = 0; r < 8; r++) {
            int node = base + r0 + r;
            if (node < n) {
                float2 v01 = unpack2(acc01[r]);
                float2 v23 = unpack2(acc23[r]);
                float4 o;
                o.x = fmaxf(v01.x + bb.x, 0.f);
                o.y = fmaxf(v01.y + bb.y, 0.f);
                o.z = fmaxf(v23.x + bb.z, 0.f);
                o.w = fmaxf(v23.y + bb.w, 0.f);
                size_t off = (size_t)node * 128 + c0;
                *(float4*)&hout[off] = o;
                store_hb(off, o);
            }
        }
    }
}

// ---------------- SpMM: warp per row, fp16 gather, fp32 accumulate ----------
__global__ void k_spmm(int n) {
    int row = (blockIdx.x * blockDim.x + threadIdx.x) >> 5;
    if (row >= n) return;
    int lane = threadIdx.x & 31;
    int beg = g_rowptr[row], end = g_rowptr[row + 1];
    float4 acc = {0.f, 0.f, 0.f, 0.f};
    int e = beg;
    for (; e + 1 < end; e += 2) {
        uint2 e0 = g_edges[e];
        uint2 e1 = g_edges[e + 1];
        float v0 = __uint_as_float(e0.y);
        float v1 = __uint_as_float(e1.y);
        uint2 x0 = *(const uint2*)&g_hb[(size_t)e0.x * 128 + lane * 4];
        uint2 x1 = *(const uint2*)&g_hb[(size_t)e1.x * 128 + lane * 4];
        float2 a0 = __half22float2(*(__half2*)&x0.x);
        float2 b0 = __half22float2(*(__half2*)&x0.y);
        float2 a1 = __half22float2(*(__half2*)&x1.x);
        float2 b1 = __half22float2(*(__half2*)&x1.y);
        acc.x += v0 * a0.x; acc.y += v0 * a0.y; acc.z += v0 * b0.x; acc.w += v0 * b0.y;
        acc.x += v1 * a1.x; acc.y += v1 * a1.y; acc.z += v1 * b1.x; acc.w += v1 * b1.y;
    }
    if (e < end) {
        uint2 e0 = g_edges[e];
        float v = __uint_as_float(e0.y);
        uint2 x0 = *(const uint2*)&g_hb[(size_t)e0.x * 128 + lane * 4];
        float2 a0 = __half22float2(*(__half2*)&x0.x);
        float2 b0 = __half22float2(*(__half2*)&x0.y);
        acc.x += v * a0.x; acc.y += v * a0.y; acc.z += v * b0.x; acc.w += v * b0.y;
    }
    *(float4*)&g_neigh[(size_t)row * 128 + lane * 4] = acc;
}

// ---------------- layer update: h += relu(h@Ws + neigh@Wn + bs + bn) --------
#define SMEM_LAYER ((2 * 128 * 128 + 2 * 128 * 32) * 4)

__global__ void __launch_bounds__(512, 1) k_layer(
    const float* __restrict__ Ws, const float* __restrict__ bs,
    const float* __restrict__ Wn, const float* __restrict__ bn,
    float* __restrict__ h, int n, int write_hb)
{
    extern __shared__ float sm[];
    float* sWs = sm;
    float* sWn = sWs + 128 * 128;
    float* sA  = sWn + 128 * 128;
    float* sB  = sA + 128 * 32;

    int tid = threadIdx.x;
    for (int i = tid; i < 128 * 128; i += 512) { sWs[i] = Ws[i]; sWn[i] = Wn[i]; }

    int base = blockIdx.x * 128;
    int c0 = (tid & 31) * 4;
    int r0 = (tid >> 5) * 8;

    u64 acc01[8], acc23[8];
    #pragma unroll
    for (int r = 0; r < 8; r++) { acc01[r] = 0ull; acc23[r] = 0ull; }

    for (int kc = 0; kc < 4; kc++) {
        __syncthreads();
        for (int i = tid; i < 128 * 32; i += 512) {
            int nd = i >> 5, k = i & 31;
            int node = base + nd;
            float a = 0.f, b = 0.f;
            if (node < n) {
                size_t off = (size_t)node * 128 + kc * 32 + k;
                a = h[off];
                b = g_neigh[off];
            }
            sA[i] = a; sB[i] = b;
        }
        __syncthreads();
        #pragma unroll 4
        for (int kk = 0; kk < 32; kk++) {
            int k = kc * 32 + kk;
            ulonglong2 ws = *(ulonglong2*)&sWs[k * 128 + c0];
            ulonglong2 wn = *(ulonglong2*)&sWn[k * 128 + c0];
            #pragma unroll
            for (int r = 0; r < 8; r++) {
                float a = sA[(r0 + r) * 32 + kk];
                float b = sB[(r0 + r) * 32 + kk];
                u64 a2 = pack2(a, a);
                u64 b2 = pack2(b, b);
                fma2(acc01[r], a2, ws.x);
                fma2(acc23[r], a2, ws.y);
                fma2(acc01[r], b2, wn.x);
                fma2(acc23[r], b2, wn.y);
            }
        }
    }

    float4 vbs = *(float4*)&bs[c0];
    float4 vbn = *(float4*)&bn[c0];
    float bx = vbs.x + vbn.x, by = vbs.y + vbn.y;
    float bz = vbs.z + vbn.z, bw = vbs.w + vbn.w;
    #pragma unroll
    for (int r = 0; r < 8; r++) {
        int node = base + r0 + r;
        if (node < n) {
            size_t off = (size_t)node * 128 + c0;
            float4* hp = (float4*)&h[off];
            float4 hv = *hp;
            float2 v01 = unpack2(acc01[r]);
            float2 v23 = unpack2(acc23[r]);
            hv.x += fmaxf(v01.x + bx, 0.f);
            hv.y += fmaxf(v01.y + by, 0.f);
            hv.z += fmaxf(v23.x + bz, 0.f);
            hv.w += fmaxf(v23.y + bw, 0.f);
            *hp = hv;
            if (write_hb) store_hb(off, hv);
        }
    }
}

// ---------------- global mean/max pool --------------------------------------
__global__ void k_reduce(const float* __restrict__ h, int n) {
    int t = threadIdx.x;  // 128
    float s = 0.f, m = 0.f;
    for (int node = blockIdx.x; node < n; node += gridDim.x) {
        float v = h[(size_t)node * 128 + t];
        s += v;
        m = fmaxf(m, v);
    }
    atomicAdd(&g_gsum[t], s);
    atomicMax(&g_gmax[t], __float_as_uint(m));
}

__global__ void k_final(float* __restrict__ out, int n) {
    int t = threadIdx.x;  // 256
    if (t < 128) out[t] = g_gsum[t] / (float)n;
    else out[t] = __uint_as_float(g_gmax[t - 128]);
}

// ---------------- launch -----------------------------------------------------
extern "C" void kernel_launch(void* const* d_in, const int* in_sizes, int n_in,
                              void* d_out, int out_size) {
    const int*   mi   = (const int*)d_in[0];
    const int*   wi   = (const int*)d_in[1];
    const int*   ti   = (const int*)d_in[2];
    const float* cont = (const float*)d_in[3];
    const int*   er   = (const int*)d_in[4];
    const int*   ec   = (const int*)d_in[5];
    const float* ev   = (const float*)d_in[6];
    const float* memb = (const float*)d_in[7];
    const float* wemb = (const float*)d_in[8];
    const float* temb = (const float*)d_in[9];
    const float* W1   = (const float*)d_in[10];
    const float* b1   = (const float*)d_in[11];
    const float* W2   = (const float*)d_in[12];
    const float* b2   = (const float*)d_in[13];
    const float* Wself  = (const float*)d_in[14];
    const float* bself  = (const float*)d_in[15];
    const float* Wneigh = (const float*)d_in[16];
    const float* bneigh = (const float*)d_in[17];

    int n = in_sizes[0];
    int e = in_sizes[4];

    float* out = (float*)d_out;
    float* h = out + 256;

    cudaFuncSetAttribute(k_input_mlp, cudaFuncAttributeMaxDynamicSharedMemorySize, SMEM_MLP);
    cudaFuncSetAttribute(k_layer, cudaFuncAttributeMaxDynamicSharedMemorySize, SMEM_LAYER);

    int ntile = (n + 127) / 128;

    k_init<<<(n + 255) / 256, 256>>>(n);
    k_hist<<<(e + 255) / 256, 256>>>(er, e);
    k_scan<<<1, 1024>>>(n);
    k_reorder<<<(e + 255) / 256, 256>>>(er, ec, ev, e);

    k_input_mlp<<<ntile, 512, SMEM_MLP>>>(mi, wi, ti, cont, memb, wemb, temb,
                                          W1, b1, W2, b2, h, n);

    for (int l = 0; l < 2; l++) {
        int nwarp_blocks = (int)(((long long)n * 32 + 255) / 256);
        k_spmm<<<nwarp_blocks, 256>>>(n);
        k_layer<<<ntile, 512, SMEM_LAYER>>>(Wself + (size_t)l * 128 * 128, bself + l * 128,
                                            Wneigh + (size_t)l * 128 * 128, bneigh + l * 128,
                                            h, n, l == 0 ? 1 : 0);
    }

    k_reduce<<<1024, 128>>>(h, n);
    k_final<<<1, 256>>>(out, n);
}

// round 4
// speedup vs baseline: 1.4000x; 1.1926x over previous
#include <cuda_runtime.h>
#include <cuda_fp16.h>

#define NMAX 200000
#define EMAX 6400000
#define HD 128

typedef unsigned long long u64;

// ---------------- f32x2 packed-FMA helpers (Blackwell FFMA2 via PTX) --------
__device__ __forceinline__ u64 pack2(float a, float b) {
    u64 r;
    asm("mov.b64 %0, {%1, %2};" : "=l"(r) : "f"(a), "f"(b));
    return r;
}
__device__ __forceinline__ void fma2(u64& d, u64 a, u64 b) {
    asm("fma.rn.f32x2 %0, %1, %2, %0;" : "+l"(d) : "l"(a), "l"(b));
}
__device__ __forceinline__ float2 unpack2(u64 v) {
    float2 f;
    asm("mov.b64 {%0, %1}, %2;" : "=f"(f.x), "=f"(f.y) : "l"(v));
    return f;
}

// ---------------- mma / ldmatrix helpers ------------------------------------
__device__ __forceinline__ unsigned smem_u32(const void* p) {
    return (unsigned)__cvta_generic_to_shared(p);
}
__device__ __forceinline__ void ldsm_x4(unsigned& r0, unsigned& r1, unsigned& r2, unsigned& r3,
                                        unsigned addr) {
    asm volatile("ldmatrix.sync.aligned.m8n8.x4.shared.b16 {%0,%1,%2,%3}, [%4];"
                 : "=r"(r0), "=r"(r1), "=r"(r2), "=r"(r3) : "r"(addr));
}
__device__ __forceinline__ void ldsm_x4_trans(unsigned& r0, unsigned& r1, unsigned& r2, unsigned& r3,
                                              unsigned addr) {
    asm volatile("ldmatrix.sync.aligned.m8n8.x4.trans.shared.b16 {%0,%1,%2,%3}, [%4];"
                 : "=r"(r0), "=r"(r1), "=r"(r2), "=r"(r3) : "r"(addr));
}
__device__ __forceinline__ void mma16816(float* d, unsigned a0, unsigned a1, unsigned a2, unsigned a3,
                                         unsigned b0, unsigned b1) {
    asm volatile("mma.sync.aligned.m16n8k16.row.col.f32.f16.f16.f32 "
                 "{%0,%1,%2,%3}, {%4,%5,%6,%7}, {%8,%9}, {%0,%1,%2,%3};"
                 : "+f"(d[0]), "+f"(d[1]), "+f"(d[2]), "+f"(d[3])
                 : "r"(a0), "r"(a1), "r"(a2), "r"(a3), "r"(b0), "r"(b1));
}

// ---------------- static device scratch (no allocations allowed) ------------
__device__ int g_cnt[NMAX];
__device__ int g_rowptr[NMAX + 1];
__device__ int g_cur[NMAX];
__device__ __align__(16) uint2 g_edges[EMAX];          // (col, val-bits)
__device__ __align__(16) float g_neigh[(size_t)NMAX * HD];
__device__ __align__(16) __half g_hb[(size_t)NMAX * HD];  // fp16 shadow of h
__device__ float g_gsum[HD];
__device__ unsigned g_gmax[HD];

// ---------------- init ------------------------------------------------------
__global__ void k_init(int n) {
    int i = blockIdx.x * blockDim.x + threadIdx.x;
    if (i < n) g_cnt[i] = 0;
    if (i < HD) { g_gsum[i] = 0.f; g_gmax[i] = 0u; }
}

// ---------------- CSR build: histogram -> scan -> reorder -------------------
__global__ void k_hist(const int* __restrict__ er, int e) {
    int i = blockIdx.x * blockDim.x + threadIdx.x;
    if (i < e) atomicAdd(&g_cnt[er[i]], 1);
}

__global__ void k_scan(int n) {
    __shared__ int s[1024];
    int tid = threadIdx.x;
    int ch = (n + 1023) >> 10;
    int st = tid * ch;
    int en = min(st + ch, n);
    int sum = 0;
    for (int i = st; i < en; i++) sum += g_cnt[i];
    s[tid] = sum;
    __syncthreads();
    for (int off = 1; off < 1024; off <<= 1) {
        int v = (tid >= off) ? s[tid - off] : 0;
        __syncthreads();
        s[tid] += v;
        __syncthreads();
    }
    int pre = (tid == 0) ? 0 : s[tid - 1];
    for (int i = st; i < en; i++) {
        g_rowptr[i] = pre;
        g_cur[i] = pre;
        pre += g_cnt[i];
    }
    if (tid == 0) g_rowptr[n] = s[1023];
}

__global__ void k_reorder(const int* __restrict__ er, const int* __restrict__ ec,
                          const float* __restrict__ ev, int e) {
    int i = blockIdx.x * blockDim.x + threadIdx.x;
    if (i < e) {
        int r = er[i];
        int p = atomicAdd(&g_cur[r], 1);
        uint2 pk;
        pk.x = (unsigned)ec[i];
        pk.y = __float_as_uint(ev[i]);
        g_edges[p] = pk;
    }
}

// ---------------- store helper: fp32 float4 -> fp16x4 (8B) ------------------
__device__ __forceinline__ void store_hb(size_t off4, float4 o) {
    __half2 p0 = __floats2half2_rn(o.x, o.y);
    __half2 p1 = __floats2half2_rn(o.z, o.w);
    uint2 pk;
    pk.x = *(unsigned*)&p0;
    pk.y = *(unsigned*)&p1;
    *(uint2*)&g_hb[off4] = pk;
}

// ---------------- fused embedding-gather + 2-layer input MLP ----------------
#define SMEM_MLP ((60 * 128 + 128 * 128 + 128 + 128 + 128 * 60 + 128 * 128) * 4)

__global__ void __launch_bounds__(512, 1) k_input_mlp(
    const int* __restrict__ mi, const int* __restrict__ wi, const int* __restrict__ ti,
    const float* __restrict__ cont,
    const float* __restrict__ memb, const float* __restrict__ wemb, const float* __restrict__ temb,
    const float* __restrict__ W1, const float* __restrict__ b1,
    const float* __restrict__ W2, const float* __restrict__ b2,
    float* __restrict__ hout, int n)
{
    extern __shared__ float sm[];
    float* sW1 = sm;
    float* sW2 = sW1 + 60 * 128;
    float* sb1 = sW2 + 128 * 128;
    float* sb2 = sb1 + 128;
    float* sx  = sb2 + 128;
    float* sh1 = sx + 128 * 60;

    int tid = threadIdx.x;
    for (int i = tid; i < 60 * 128; i += 512) sW1[i] = W1[i];
    for (int i = tid; i < 128 * 128; i += 512) sW2[i] = W2[i];
    if (tid < 128) { sb1[tid] = b1[tid]; sb2[tid] = b2[tid]; }

    int base = blockIdx.x * 128;
    for (int i = tid; i < 128 * 60; i += 512) {
        int nd = i / 60, f = i - nd * 60;
        int node = base + nd;
        float v = 0.f;
        if (node < n) {
            if (f < 16)       v = memb[mi[node] * 16 + f];
            else if (f < 32)  v = wemb[wi[node] * 16 + (f - 16)];
            else if (f < 48)  v = temb[ti[node] * 16 + (f - 32)];
            else              v = cont[(size_t)node * 12 + (f - 48)];
        }
        sx[i] = v;
    }
    __syncthreads();

    int c0 = (tid & 31) * 4;
    int r0 = (tid >> 5) * 8;

    u64 acc01[8], acc23[8];
    #pragma unroll
    for (int r = 0; r < 8; r++) { acc01[r] = 0ull; acc23[r] = 0ull; }

    #pragma unroll 4
    for (int k = 0; k < 60; k++) {
        ulonglong2 w = *(ulonglong2*)&sW1[k * 128 + c0];
        #pragma unroll
        for (int r = 0; r < 8; r++) {
            float a = sx[(r0 + r) * 60 + k];
            u64 a2 = pack2(a, a);
            fma2(acc01[r], a2, w.x);
            fma2(acc23[r], a2, w.y);
        }
    }
    {
        float4 bb = *(float4*)&sb1[c0];
        #pragma unroll
        for (int r = 0; r < 8; r++) {
            float2 v01 = unpack2(acc01[r]);
            float2 v23 = unpack2(acc23[r]);
            float4 o;
            o.x = fmaxf(v01.x + bb.x, 0.f);
            o.y = fmaxf(v01.y + bb.y, 0.f);
            o.z = fmaxf(v23.x + bb.z, 0.f);
            o.w = fmaxf(v23.y + bb.w, 0.f);
            *(float4*)&sh1[(r0 + r) * 128 + c0] = o;
        }
    }
    __syncthreads();

    #pragma unroll
    for (int r = 0; r < 8; r++) { acc01[r] = 0ull; acc23[r] = 0ull; }

    #pragma unroll 4
    for (int k = 0; k < 128; k++) {
        ulonglong2 w = *(ulonglong2*)&sW2[k * 128 + c0];
        #pragma unroll
        for (int r = 0; r < 8; r++) {
            float a = sh1[(r0 + r) * 128 + k];
            u64 a2 = pack2(a, a);
            fma2(acc01[r], a2, w.x);
            fma2(acc23[r], a2, w.y);
        }
    }
    {
        float4 bb = *(float4*)&sb2[c0];
        #pragma unroll
        for (int r = 0; r < 8; r++) {
            int node = base + r0 + r;
            if (node < n) {
                float2 v01 = unpack2(acc01[r]);
                float2 v23 = unpack2(acc23[r]);
                float4 o;
                o.x = fmaxf(v01.x + bb.x, 0.f);
                o.y = fmaxf(v01.y + bb.y, 0.f);
                o.z = fmaxf(v23.x + bb.z, 0.f);
                o.w = fmaxf(v23.y + bb.w, 0.f);
                size_t off = (size_t)node * 128 + c0;
                *(float4*)&hout[off] = o;
                store_hb(off, o);
            }
        }
    }
}

// ---------------- SpMM: half-warp per row, fp16 16B gathers -----------------
__global__ void k_spmm(int n) {
    int row = (blockIdx.x * blockDim.x + threadIdx.x) >> 4;
    if (row >= n) return;
    int s = threadIdx.x & 15;      // sub-lane: covers 8 halves
    int beg = g_rowptr[row], end = g_rowptr[row + 1];
    float acc0 = 0.f, acc1 = 0.f, acc2 = 0.f, acc3 = 0.f;
    float acc4 = 0.f, acc5 = 0.f, acc6 = 0.f, acc7 = 0.f;
    int e = beg;
    for (; e + 1 < end; e += 2) {
        uint2 e0 = g_edges[e];
        uint2 e1 = g_edges[e + 1];
        float v0 = __uint_as_float(e0.y);
        float v1 = __uint_as_float(e1.y);
        uint4 x0 = *(const uint4*)&g_hb[(size_t)e0.x * 128 + s * 8];
        uint4 x1 = *(const uint4*)&g_hb[(size_t)e1.x * 128 + s * 8];
        float2 p;
        p = __half22float2(*(__half2*)&x0.x); acc0 += v0 * p.x; acc1 += v0 * p.y;
        p = __half22float2(*(__half2*)&x0.y); acc2 += v0 * p.x; acc3 += v0 * p.y;
        p = __half22float2(*(__half2*)&x0.z); acc4 += v0 * p.x; acc5 += v0 * p.y;
        p = __half22float2(*(__half2*)&x0.w); acc6 += v0 * p.x; acc7 += v0 * p.y;
        p = __half22float2(*(__half2*)&x1.x); acc0 += v1 * p.x; acc1 += v1 * p.y;
        p = __half22float2(*(__half2*)&x1.y); acc2 += v1 * p.x; acc3 += v1 * p.y;
        p = __half22float2(*(__half2*)&x1.z); acc4 += v1 * p.x; acc5 += v1 * p.y;
        p = __half22float2(*(__half2*)&x1.w); acc6 += v1 * p.x; acc7 += v1 * p.y;
    }
    if (e < end) {
        uint2 e0 = g_edges[e];
        float v0 = __uint_as_float(e0.y);
        uint4 x0 = *(const uint4*)&g_hb[(size_t)e0.x * 128 + s * 8];
        float2 p;
        p = __half22float2(*(__half2*)&x0.x); acc0 += v0 * p.x; acc1 += v0 * p.y;
        p = __half22float2(*(__half2*)&x0.y); acc2 += v0 * p.x; acc3 += v0 * p.y;
        p = __half22float2(*(__half2*)&x0.z); acc4 += v0 * p.x; acc5 += v0 * p.y;
        p = __half22float2(*(__half2*)&x0.w); acc6 += v0 * p.x; acc7 += v0 * p.y;
    }
    size_t off = (size_t)row * 128 + s * 8;
    float4 o0 = {acc0, acc1, acc2, acc3};
    float4 o1 = {acc4, acc5, acc6, acc7};
    *(float4*)&g_neigh[off] = o0;
    *(float4*)&g_neigh[off + 4] = o1;
}

// ---------------- tensor-core layer: h += relu([h;neigh]@[Ws;Wn] + b) -------
// smem: sW fp16 [256][136], sA fp16 [128][264]
#define WSTR 136
#define ASTR 264
#define SMEM_TC (256 * WSTR * 2 + 128 * ASTR * 2)

__global__ void __launch_bounds__(256, 1) k_layer_tc(
    const float* __restrict__ Ws, const float* __restrict__ bs,
    const float* __restrict__ Wn, const float* __restrict__ bn,
    float* __restrict__ h, int n, int write_hb)
{
    extern __shared__ __half smh[];
    __half* sW = smh;                 // [256][WSTR]
    __half* sA = smh + 256 * WSTR;    // [128][ASTR]

    int tid = threadIdx.x;
    int base = blockIdx.x * 128;

    // stage W: rows 0..127 = Ws[k][n], rows 128..255 = Wn[k][n]
    for (int i = tid; i < 128 * 128; i += 256) {
        int k = i >> 7, c = i & 127;
        sW[k * WSTR + c] = __float2half(Ws[i]);
        sW[(k + 128) * WSTR + c] = __float2half(Wn[i]);
    }
    // stage A: cols 0..127 = h, cols 128..255 = neigh
    for (int i = tid; i < 128 * 128; i += 256) {
        int nd = i >> 7, k = i & 127;
        int node = base + nd;
        float a = 0.f, b = 0.f;
        if (node < n) {
            size_t off = (size_t)node * 128 + k;
            a = h[off];
            b = g_neigh[off];
        }
        sA[nd * ASTR + k] = __float2half(a);
        sA[nd * ASTR + 128 + k] = __float2half(b);
    }
    __syncthreads();

    int wid = tid >> 5;        // 0..7 -> rows wid*16..wid*16+15
    int lane = tid & 31;
    int m0 = wid * 16;

    float acc[16][4];
    #pragma unroll
    for (int t = 0; t < 16; t++)
        #pragma unroll
        for (int c = 0; c < 4; c++) acc[t][c] = 0.f;

    // ldmatrix lane address components
    int lg = lane >> 3;          // group 0..3
    int lr = lane & 7;
    // A: row = m0 + lr + (lg&1)*8 ; colHalf = k0 + (lg>>1)*8
    int a_row = m0 + lr + (lg & 1) * 8;
    int a_colb = (lg >> 1) * 8;
    // B: row = k0 + lr + (lg&1)*8 ; col = npair*16 + (lg>>1)*8
    int b_rowb = lr + (lg & 1) * 8;
    int b_colb = (lg >> 1) * 8;

    unsigned sA_base = smem_u32(sA);
    unsigned sW_base = smem_u32(sW);

    #pragma unroll 1
    for (int ks = 0; ks < 16; ks++) {
        int k0 = ks * 16;
        unsigned a0, a1, a2, a3;
        ldsm_x4(a0, a1, a2, a3, sA_base + (unsigned)(a_row * ASTR + k0 + a_colb) * 2u);
        #pragma unroll
        for (int j = 0; j < 8; j++) {
            unsigned b0, b1, b2, b3;
            ldsm_x4_trans(b0, b1, b2, b3,
                          sW_base + (unsigned)((k0 + b_rowb) * WSTR + j * 16 + b_colb) * 2u);
            mma16816(acc[2 * j], a0, a1, a2, a3, b0, b1);
            mma16816(acc[2 * j + 1], a0, a1, a2, a3, b2, b3);
        }
    }

    // epilogue: d0,d1 -> (row0, c..c+1); d2,d3 -> (row0+8, c..c+1)
    int row0 = m0 + (lane >> 2);
    int cbase = (lane & 3) * 2;
    int node0 = base + row0;
    int node1 = node0 + 8;
    #pragma unroll
    for (int t = 0; t < 16; t++) {
        int col = t * 8 + cbase;
        float bsum0 = bs[col] + bn[col];
        float bsum1 = bs[col + 1] + bn[col + 1];
        if (node0 < n) {
            size_t off = (size_t)node0 * 128 + col;
            float2* p = (float2*)&h[off];
            float2 hv = *p;
            hv.x += fmaxf(acc[t][0] + bsum0, 0.f);
            hv.y += fmaxf(acc[t][1] + bsum1, 0.f);
            *p = hv;
            if (write_hb) {
                __half2 hh = __floats2half2_rn(hv.x, hv.y);
                *(__half2*)&g_hb[off] = hh;
            }
        }
        if (node1 < n) {
            size_t off = (size_t)node1 * 128 + col;
            float2* p = (float2*)&h[off];
            float2 hv = *p;
            hv.x += fmaxf(acc[t][2] + bsum0, 0.f);
            hv.y += fmaxf(acc[t][3] + bsum1, 0.f);
            *p = hv;
            if (write_hb) {
                __half2 hh = __floats2half2_rn(hv.x, hv.y);
                *(__half2*)&g_hb[off] = hh;
            }
        }
    }
}

// ---------------- global mean/max pool --------------------------------------
__global__ void k_reduce(const float* __restrict__ h, int n) {
    int t = threadIdx.x;  // 128
    float s = 0.f, m = 0.f;
    for (int node = blockIdx.x; node < n; node += gridDim.x) {
        float v = h[(size_t)node * 128 + t];
        s += v;
        m = fmaxf(m, v);
    }
    atomicAdd(&g_gsum[t], s);
    atomicMax(&g_gmax[t], __float_as_uint(m));
}

__global__ void k_final(float* __restrict__ out, int n) {
    int t = threadIdx.x;  // 256
    if (t < 128) out[t] = g_gsum[t] / (float)n;
    else out[t] = __uint_as_float(g_gmax[t - 128]);
}

// ---------------- launch -----------------------------------------------------
extern "C" void kernel_launch(void* const* d_in, const int* in_sizes, int n_in,
                              void* d_out, int out_size) {
    const int*   mi   = (const int*)d_in[0];
    const int*   wi   = (const int*)d_in[1];
    const int*   ti   = (const int*)d_in[2];
    const float* cont = (const float*)d_in[3];
    const int*   er   = (const int*)d_in[4];
    const int*   ec   = (const int*)d_in[5];
    const float* ev   = (const float*)d_in[6];
    const float* memb = (const float*)d_in[7];
    const float* wemb = (const float*)d_in[8];
    const float* temb = (const float*)d_in[9];
    const float* W1   = (const float*)d_in[10];
    const float* b1   = (const float*)d_in[11];
    const float* W2   = (const float*)d_in[12];
    const float* b2   = (const float*)d_in[13];
    const float* Wself  = (const float*)d_in[14];
    const float* bself  = (const float*)d_in[15];
    const float* Wneigh = (const float*)d_in[16];
    const float* bneigh = (const float*)d_in[17];

    int n = in_sizes[0];
    int e = in_sizes[4];

    float* out = (float*)d_out;
    float* h = out + 256;

    cudaFuncSetAttribute(k_input_mlp, cudaFuncAttributeMaxDynamicSharedMemorySize, SMEM_MLP);
    cudaFuncSetAttribute(k_layer_tc, cudaFuncAttributeMaxDynamicSharedMemorySize, SMEM_TC);

    int ntile = (n + 127) / 128;

    k_init<<<(n + 255) / 256, 256>>>(n);
    k_hist<<<(e + 255) / 256, 256>>>(er, e);
    k_scan<<<1, 1024>>>(n);
    k_reorder<<<(e + 255) / 256, 256>>>(er, ec, ev, e);

    k_input_mlp<<<ntile, 512, SMEM_MLP>>>(mi, wi, ti, cont, memb, wemb, temb,
                                          W1, b1, W2, b2, h, n);

    for (int l = 0; l < 2; l++) {
        int hw_blocks = (int)(((long long)n * 16 + 255) / 256);
        k_spmm<<<hw_blocks, 256>>>(n);
        k_layer_tc<<<ntile, 256, SMEM_TC>>>(Wself + (size_t)l * 128 * 128, bself + l * 128,
                                            Wneigh + (size_t)l * 128 * 128, bneigh + l * 128,
                                            h, n, l == 0 ? 1 : 0);
    }

    k_reduce<<<1024, 128>>>(h, n);
    k_final<<<1, 256>>>(out, n);
}

// round 5
// speedup vs baseline: 1.8341x; 1.3101x over previous
#include <cuda_runtime.h>
#include <cuda_fp16.h>

#define NMAX 200000
#define EMAX 6400000
#define HD 128

// ---------------- mma / ldmatrix helpers ------------------------------------
__device__ __forceinline__ unsigned smem_u32(const void* p) {
    return (unsigned)__cvta_generic_to_shared(p);
}
__device__ __forceinline__ void ldsm_x4(unsigned& r0, unsigned& r1, unsigned& r2, unsigned& r3,
                                        unsigned addr) {
    asm volatile("ldmatrix.sync.aligned.m8n8.x4.shared.b16 {%0,%1,%2,%3}, [%4];"
                 : "=r"(r0), "=r"(r1), "=r"(r2), "=r"(r3) : "r"(addr));
}
__device__ __forceinline__ void ldsm_x4_trans(unsigned& r0, unsigned& r1, unsigned& r2, unsigned& r3,
                                              unsigned addr) {
    asm volatile("ldmatrix.sync.aligned.m8n8.x4.trans.shared.b16 {%0,%1,%2,%3}, [%4];"
                 : "=r"(r0), "=r"(r1), "=r"(r2), "=r"(r3) : "r"(addr));
}
__device__ __forceinline__ void mma16816(float* d, unsigned a0, unsigned a1, unsigned a2, unsigned a3,
                                         unsigned b0, unsigned b1) {
    asm volatile("mma.sync.aligned.m16n8k16.row.col.f32.f16.f16.f32 "
                 "{%0,%1,%2,%3}, {%4,%5,%6,%7}, {%8,%9}, {%0,%1,%2,%3};"
                 : "+f"(d[0]), "+f"(d[1]), "+f"(d[2]), "+f"(d[3])
                 : "r"(a0), "r"(a1), "r"(a2), "r"(a3), "r"(b0), "r"(b1));
}

// ---------------- static device scratch (no allocations allowed) ------------
__device__ int g_cnt[NMAX];
__device__ int g_rowptr[NMAX + 1];
__device__ int g_cur[NMAX];
__device__ int g_part[256];
__device__ int g_partoff[256];
__device__ __align__(16) uint2 g_edges[EMAX];              // (col, val-bits)
__device__ __align__(16) __half g_neighh[(size_t)NMAX * HD];  // fp16 neighbor agg
__device__ __align__(16) __half g_hb[(size_t)NMAX * HD];      // fp16 shadow of h
__device__ __align__(16) __half g_w1h[64 * 128];              // padded W1 fp16
__device__ __align__(16) __half g_w2h[128 * 128];
__device__ __align__(16) __half g_wlh[2 * 256 * 128];         // [l][Ws;Wn][128]
__device__ float g_gsum[HD];
__device__ unsigned g_gmax[HD];

// ---------------- init ------------------------------------------------------
__global__ void k_init(int n) {
    int i = blockIdx.x * blockDim.x + threadIdx.x;
    if (i < n) g_cnt[i] = 0;
    if (i < HD) { g_gsum[i] = 0.f; g_gmax[i] = 0u; }
}

// ---------------- weight fp16 pre-conversion --------------------------------
__global__ void k_prep(const float* __restrict__ W1, const float* __restrict__ W2,
                       const float* __restrict__ Wself, const float* __restrict__ Wneigh) {
    int i = blockIdx.x * blockDim.x + threadIdx.x;
    if (i < 64 * 128) {
        int r = i >> 7, c = i & 127;
        g_w1h[i] = __float2half(r < 60 ? W1[r * 128 + c] : 0.f);
    } else if (i < 64 * 128 + 128 * 128) {
        int j = i - 64 * 128;
        g_w2h[j] = __float2half(W2[j]);
    } else if (i < 64 * 128 + 128 * 128 + 2 * 256 * 128) {
        int j = i - 64 * 128 - 128 * 128;
        int l = j >> 15;
        int r = (j & 32767) >> 7;
        int c = j & 127;
        float v = (r < 128) ? Wself[l * 16384 + r * 128 + c]
                            : Wneigh[l * 16384 + (r - 128) * 128 + c];
        g_wlh[j] = __float2half(v);
    }
}

// ---------------- CSR build: histogram -> parallel scan -> reorder ----------
__global__ void k_hist(const int* __restrict__ er, int e) {
    int i = blockIdx.x * blockDim.x + threadIdx.x;
    if (i < e) atomicAdd(&g_cnt[er[i]], 1);
}

__global__ void k_scanA(int n) {  // per-1024-chunk sums
    __shared__ int s[256];
    int b = blockIdx.x, t = threadIdx.x;
    int i0 = b * 1024 + t * 4;
    int sum = 0;
    #pragma unroll
    for (int j = 0; j < 4; j++) { int i = i0 + j; if (i < n) sum += g_cnt[i]; }
    s[t] = sum;
    __syncthreads();
    for (int off = 128; off > 0; off >>= 1) {
        if (t < off) s[t] += s[t + off];
        __syncthreads();
    }
    if (t == 0) g_part[b] = s[0];
}

__global__ void k_scanB(int nb, int n) {  // scan partials (nb <= 256)
    __shared__ int s[256];
    int t = threadIdx.x;
    int v = (t < nb) ? g_part[t] : 0;
    s[t] = v;
    __syncthreads();
    for (int off = 1; off < 256; off <<= 1) {
        int u = (t >= off) ? s[t - off] : 0;
        __syncthreads();
        s[t] += u;
        __syncthreads();
    }
    if (t < nb) g_partoff[t] = s[t] - v;
    if (t == 255) g_rowptr[n] = s[255];
}

__global__ void k_scanC(int n) {  // final exclusive scan + write
    __shared__ int s[256];
    int b = blockIdx.x, t = threadIdx.x;
    int i0 = b * 1024 + t * 4;
    int c[4]; int sum = 0;
    #pragma unroll
    for (int j = 0; j < 4; j++) { int i = i0 + j; c[j] = (i < n) ? g_cnt[i] : 0; sum += c[j]; }
    s[t] = sum;
    __syncthreads();
    for (int off = 1; off < 256; off <<= 1) {
        int u = (t >= off) ? s[t - off] : 0;
        __syncthreads();
        s[t] += u;
        __syncthreads();
    }
    int pre = g_partoff[b] + s[t] - sum;
    #pragma unroll
    for (int j = 0; j < 4; j++) {
        int i = i0 + j;
        if (i < n) { g_rowptr[i] = pre; g_cur[i] = pre; pre += c[j]; }
    }
}

__global__ void k_reorder(const int* __restrict__ er, const int* __restrict__ ec,
                          const float* __restrict__ ev, int e) {
    int i = blockIdx.x * blockDim.x + threadIdx.x;
    if (i < e) {
        int r = er[i];
        int p = atomicAdd(&g_cur[r], 1);
        uint2 pk;
        pk.x = (unsigned)ec[i];
        pk.y = __float_as_uint(ev[i]);
        g_edges[p] = pk;
    }
}

// ---------------- tensor-core input MLP -------------------------------------
// smem: sX [128][72]h, sW1 [64][136]h, sW2 [128][136]h, sH1 [128][136]h
#define XSTR 72
#define WSTR 136
#define SMEM_MLP_TC ((128 * XSTR + 64 * WSTR + 128 * WSTR + 128 * WSTR) * 2)

__global__ void __launch_bounds__(256, 1) k_mlp_tc(
    const int* __restrict__ mi, const int* __restrict__ wi, const int* __restrict__ ti,
    const float* __restrict__ cont,
    const float* __restrict__ memb, const float* __restrict__ wemb, const float* __restrict__ temb,
    const float* __restrict__ b1, const float* __restrict__ b2,
    float* __restrict__ hout, int n)
{
    extern __shared__ __half smh[];
    __half* sX  = smh;                        // [128][72]
    __half* sW1 = sX + 128 * XSTR;            // [64][136]
    __half* sW2 = sW1 + 64 * WSTR;            // [128][136]
    __half* sH1 = sW2 + 128 * WSTR;           // [128][136]

    int tid = threadIdx.x;
    int base = blockIdx.x * 128;

    // stage weights (uint4 copies from fp16 tables)
    for (int i = tid; i < 64 * 16; i += 256) {
        int r = i >> 4, q = i & 15;
        *(uint4*)&sW1[r * WSTR + q * 8] = *(const uint4*)&g_w1h[i * 8];
    }
    for (int i = tid; i < 128 * 16; i += 256) {
        int r = i >> 4, q = i & 15;
        *(uint4*)&sW2[r * WSTR + q * 8] = *(const uint4*)&g_w2h[i * 8];
    }
    // gather x tile -> fp16 [128][64] (cols 60..63 zero)
    for (int i = tid; i < 128 * 64; i += 256) {
        int nd = i >> 6, f = i & 63;
        int node = base + nd;
        float v = 0.f;
        if (node < n && f < 60) {
            if (f < 16)       v = memb[mi[node] * 16 + f];
            else if (f < 32)  v = wemb[wi[node] * 16 + (f - 16)];
            else if (f < 48)  v = temb[ti[node] * 16 + (f - 32)];
            else              v = cont[(size_t)node * 12 + (f - 48)];
        }
        sX[nd * XSTR + f] = __float2half(v);
    }
    __syncthreads();

    int wid = tid >> 5;
    int lane = tid & 31;
    int m0 = wid * 16;
    int lg = lane >> 3, lr = lane & 7;
    int a_row = m0 + lr + (lg & 1) * 8;
    int a_colb = (lg >> 1) * 8;
    int b_rowb = lr + (lg & 1) * 8;
    int b_colb = (lg >> 1) * 8;
    int row0 = m0 + (lane >> 2);
    int cbase = (lane & 3) * 2;

    unsigned sX_b = smem_u32(sX);
    unsigned sW1_b = smem_u32(sW1);
    unsigned sW2_b = smem_u32(sW2);
    unsigned sH1_b = smem_u32(sH1);

    float acc[16][4];
    #pragma unroll
    for (int t = 0; t < 16; t++)
        #pragma unroll
        for (int c = 0; c < 4; c++) acc[t][c] = 0.f;

    // GEMM1: [128x64] @ [64x128]
    #pragma unroll
    for (int ks = 0; ks < 4; ks++) {
        int k0 = ks * 16;
        unsigned a0, a1, a2, a3;
        ldsm_x4(a0, a1, a2, a3, sX_b + (unsigned)(a_row * XSTR + k0 + a_colb) * 2u);
        #pragma unroll
        for (int j = 0; j < 8; j++) {
            unsigned b0, b1r, b2r, b3;
            ldsm_x4_trans(b0, b1r, b2r, b3,
                          sW1_b + (unsigned)((k0 + b_rowb) * WSTR + j * 16 + b_colb) * 2u);
            mma16816(acc[2 * j], a0, a1, a2, a3, b0, b1r);
            mma16816(acc[2 * j + 1], a0, a1, a2, a3, b2r, b3);
        }
    }
    // epilogue1: relu + bias -> sH1 fp16
    #pragma unroll
    for (int t = 0; t < 16; t++) {
        int col = t * 8 + cbase;
        float bb0 = b1[col], bb1 = b1[col + 1];
        __half2 h0 = __floats2half2_rn(fmaxf(acc[t][0] + bb0, 0.f), fmaxf(acc[t][1] + bb1, 0.f));
        __half2 h1v = __floats2half2_rn(fmaxf(acc[t][2] + bb0, 0.f), fmaxf(acc[t][3] + bb1, 0.f));
        *(__half2*)&sH1[row0 * WSTR + col] = h0;
        *(__half2*)&sH1[(row0 + 8) * WSTR + col] = h1v;
    }
    __syncthreads();

    #pragma unroll
    for (int t = 0; t < 16; t++)
        #pragma unroll
        for (int c = 0; c < 4; c++) acc[t][c] = 0.f;

    // GEMM2: [128x128] @ [128x128]
    #pragma unroll 1
    for (int ks = 0; ks < 8; ks++) {
        int k0 = ks * 16;
        unsigned a0, a1, a2, a3;
        ldsm_x4(a0, a1, a2, a3, sH1_b + (unsigned)(a_row * WSTR + k0 + a_colb) * 2u);
        #pragma unroll
        for (int j = 0; j < 8; j++) {
            unsigned b0, b1r, b2r, b3;
            ldsm_x4_trans(b0, b1r, b2r, b3,
                          sW2_b + (unsigned)((k0 + b_rowb) * WSTR + j * 16 + b_colb) * 2u);
            mma16816(acc[2 * j], a0, a1, a2, a3, b0, b1r);
            mma16816(acc[2 * j + 1], a0, a1, a2, a3, b2r, b3);
        }
    }
    // epilogue2: relu + bias -> h fp32 + g_hb fp16
    int node0 = base + row0;
    int node1 = node0 + 8;
    #pragma unroll
    for (int t = 0; t < 16; t++) {
        int col = t * 8 + cbase;
        float bb0 = b2[col], bb1 = b2[col + 1];
        if (node0 < n) {
            float x = fmaxf(acc[t][0] + bb0, 0.f);
            float y = fmaxf(acc[t][1] + bb1, 0.f);
            size_t off = (size_t)node0 * 128 + col;
            *(float2*)&hout[off] = make_float2(x, y);
            *(__half2*)&g_hb[off] = __floats2half2_rn(x, y);
        }
        if (node1 < n) {
            float x = fmaxf(acc[t][2] + bb0, 0.f);
            float y = fmaxf(acc[t][3] + bb1, 0.f);
            size_t off = (size_t)node1 * 128 + col;
            *(float2*)&hout[off] = make_float2(x, y);
            *(__half2*)&g_hb[off] = __floats2half2_rn(x, y);
        }
    }
}

// ---------------- SpMM: half-warp per row, fp16 in, fp16 out ----------------
__global__ void k_spmm(int n) {
    int row = (blockIdx.x * blockDim.x + threadIdx.x) >> 4;
    if (row >= n) return;
    int s = threadIdx.x & 15;
    int beg = g_rowptr[row], end = g_rowptr[row + 1];
    float acc0 = 0.f, acc1 = 0.f, acc2 = 0.f, acc3 = 0.f;
    float acc4 = 0.f, acc5 = 0.f, acc6 = 0.f, acc7 = 0.f;
    int e = beg;
    for (; e + 1 < end; e += 2) {
        uint2 e0 = g_edges[e];
        uint2 e1 = g_edges[e + 1];
        float v0 = __uint_as_float(e0.y);
        float v1 = __uint_as_float(e1.y);
        uint4 x0 = *(const uint4*)&g_hb[(size_t)e0.x * 128 + s * 8];
        uint4 x1 = *(const uint4*)&g_hb[(size_t)e1.x * 128 + s * 8];
        float2 p;
        p = __half22float2(*(__half2*)&x0.x); acc0 += v0 * p.x; acc1 += v0 * p.y;
        p = __half22float2(*(__half2*)&x0.y); acc2 += v0 * p.x; acc3 += v0 * p.y;
        p = __half22float2(*(__half2*)&x0.z); acc4 += v0 * p.x; acc5 += v0 * p.y;
        p = __half22float2(*(__half2*)&x0.w); acc6 += v0 * p.x; acc7 += v0 * p.y;
        p = __half22float2(*(__half2*)&x1.x); acc0 += v1 * p.x; acc1 += v1 * p.y;
        p = __half22float2(*(__half2*)&x1.y); acc2 += v1 * p.x; acc3 += v1 * p.y;
        p = __half22float2(*(__half2*)&x1.z); acc4 += v1 * p.x; acc5 += v1 * p.y;
        p = __half22float2(*(__half2*)&x1.w); acc6 += v1 * p.x; acc7 += v1 * p.y;
    }
    if (e < end) {
        uint2 e0 = g_edges[e];
        float v0 = __uint_as_float(e0.y);
        uint4 x0 = *(const uint4*)&g_hb[(size_t)e0.x * 128 + s * 8];
        float2 p;
        p = __half22float2(*(__half2*)&x0.x); acc0 += v0 * p.x; acc1 += v0 * p.y;
        p = __half22float2(*(__half2*)&x0.y); acc2 += v0 * p.x; acc3 += v0 * p.y;
        p = __half22float2(*(__half2*)&x0.z); acc4 += v0 * p.x; acc5 += v0 * p.y;
        p = __half22float2(*(__half2*)&x0.w); acc6 += v0 * p.x; acc7 += v0 * p.y;
    }
    uint4 o;
    __half2 h0 = __floats2half2_rn(acc0, acc1);
    __half2 h1 = __floats2half2_rn(acc2, acc3);
    __half2 h2 = __floats2half2_rn(acc4, acc5);
    __half2 h3 = __floats2half2_rn(acc6, acc7);
    o.x = *(unsigned*)&h0; o.y = *(unsigned*)&h1;
    o.z = *(unsigned*)&h2; o.w = *(unsigned*)&h3;
    *(uint4*)&g_neighh[(size_t)row * 128 + s * 8] = o;
}

// ---------------- tensor-core layer: h += relu([h;neigh]@[Ws;Wn] + b) -------
#define ASTR 264
#define SMEM_TC ((256 * WSTR + 128 * ASTR) * 2)

__global__ void __launch_bounds__(256, 1) k_layer_tc(
    const __half* __restrict__ wl, const float* __restrict__ bs, const float* __restrict__ bn,
    float* __restrict__ h, int n, int write_hb)
{
    extern __shared__ __half smh[];
    __half* sW = smh;                 // [256][136]
    __half* sA = smh + 256 * WSTR;    // [128][264]

    int tid = threadIdx.x;
    int base = blockIdx.x * 128;

    // stage W (uint4 copies): [256][128] -> [256][136]
    for (int i = tid; i < 256 * 16; i += 256) {
        int r = i >> 4, q = i & 15;
        *(uint4*)&sW[r * WSTR + q * 8] = *(const uint4*)&g_wlh[(size_t)(&wl[0] - &g_wlh[0]) + i * 8];
    }
    // stage A: cols 0..127 = h (fp16 shadow), 128..255 = neigh (fp16)
    for (int i = tid; i < 128 * 32; i += 256) {
        int nd = i >> 5, q = i & 31;
        int node = base + nd;
        uint4 v = {0u, 0u, 0u, 0u};
        if (node < n) {
            if (q < 16) v = *(const uint4*)&g_hb[(size_t)node * 128 + q * 8];
            else        v = *(const uint4*)&g_neighh[(size_t)node * 128 + (q - 16) * 8];
        }
        *(uint4*)&sA[nd * ASTR + q * 8] = v;
    }
    __syncthreads();

    int wid = tid >> 5;
    int lane = tid & 31;
    int m0 = wid * 16;
    int lg = lane >> 3, lr = lane & 7;
    int a_row = m0 + lr + (lg & 1) * 8;
    int a_colb = (lg >> 1) * 8;
    int b_rowb = lr + (lg & 1) * 8;
    int b_colb = (lg >> 1) * 8;

    unsigned sA_b = smem_u32(sA);
    unsigned sW_b = smem_u32(sW);

    float acc[16][4];
    #pragma unroll
    for (int t = 0; t < 16; t++)
        #pragma unroll
        for (int c = 0; c < 4; c++) acc[t][c] = 0.f;

    #pragma unroll 1
    for (int ks = 0; ks < 16; ks++) {
        int k0 = ks * 16;
        unsigned a0, a1, a2, a3;
        ldsm_x4(a0, a1, a2, a3, sA_b + (unsigned)(a_row * ASTR + k0 + a_colb) * 2u);
        #pragma unroll
        for (int j = 0; j < 8; j++) {
            unsigned b0, b1, b2, b3;
            ldsm_x4_trans(b0, b1, b2, b3,
                          sW_b + (unsigned)((k0 + b_rowb) * WSTR + j * 16 + b_colb) * 2u);
            mma16816(acc[2 * j], a0, a1, a2, a3, b0, b1);
            mma16816(acc[2 * j + 1], a0, a1, a2, a3, b2, b3);
        }
    }

    int row0 = m0 + (lane >> 2);
    int cbase = (lane & 3) * 2;
    int node0 = base + row0;
    int node1 = node0 + 8;
    #pragma unroll
    for (int t = 0; t < 16; t++) {
        int col = t * 8 + cbase;
        float bsum0 = bs[col] + bn[col];
        float bsum1 = bs[col + 1] + bn[col + 1];
        if (node0 < n) {
            size_t off = (size_t)node0 * 128 + col;
            float2* p = (float2*)&h[off];
            float2 hv = *p;
            hv.x += fmaxf(acc[t][0] + bsum0, 0.f);
            hv.y += fmaxf(acc[t][1] + bsum1, 0.f);
            *p = hv;
            if (write_hb) *(__half2*)&g_hb[off] = __floats2half2_rn(hv.x, hv.y);
        }
        if (node1 < n) {
            size_t off = (size_t)node1 * 128 + col;
            float2* p = (float2*)&h[off];
            float2 hv = *p;
            hv.x += fmaxf(acc[t][2] + bsum0, 0.f);
            hv.y += fmaxf(acc[t][3] + bsum1, 0.f);
            *p = hv;
            if (write_hb) *(__half2*)&g_hb[off] = __floats2half2_rn(hv.x, hv.y);
        }
    }
}

// ---------------- global mean/max pool --------------------------------------
__global__ void k_reduce(const float* __restrict__ h, int n) {
    int t = threadIdx.x;  // 128
    float s = 0.f, m = 0.f;
    for (int node = blockIdx.x; node < n; node += gridDim.x) {
        float v = h[(size_t)node * 128 + t];
        s += v;
        m = fmaxf(m, v);
    }
    atomicAdd(&g_gsum[t], s);
    atomicMax(&g_gmax[t], __float_as_uint(m));
}

__global__ void k_final(float* __restrict__ out, int n) {
    int t = threadIdx.x;  // 256
    if (t < 128) out[t] = g_gsum[t] / (float)n;
    else out[t] = __uint_as_float(g_gmax[t - 128]);
}

// ---------------- launch -----------------------------------------------------
extern "C" void kernel_launch(void* const* d_in, const int* in_sizes, int n_in,
                              void* d_out, int out_size) {
    const int*   mi   = (const int*)d_in[0];
    const int*   wi   = (const int*)d_in[1];
    const int*   ti   = (const int*)d_in[2];
    const float* cont = (const float*)d_in[3];
    const int*   er   = (const int*)d_in[4];
    const int*   ec   = (const int*)d_in[5];
    const float* ev   = (const float*)d_in[6];
    const float* memb = (const float*)d_in[7];
    const float* wemb = (const float*)d_in[8];
    const float* temb = (const float*)d_in[9];
    const float* W1   = (const float*)d_in[10];
    const float* b1   = (const float*)d_in[11];
    const float* W2   = (const float*)d_in[12];
    const float* b2   = (const float*)d_in[13];
    const float* Wself  = (const float*)d_in[14];
    const float* bself  = (const float*)d_in[15];
    const float* Wneigh = (const float*)d_in[16];
    const float* bneigh = (const float*)d_in[17];

    int n = in_sizes[0];
    int e = in_sizes[4];

    float* out = (float*)d_out;
    float* h = out + 256;

    cudaFuncSetAttribute(k_mlp_tc, cudaFuncAttributeMaxDynamicSharedMemorySize, SMEM_MLP_TC);
    cudaFuncSetAttribute(k_layer_tc, cudaFuncAttributeMaxDynamicSharedMemorySize, SMEM_TC);

    int ntile = (n + 127) / 128;
    int nchunk = (n + 1023) / 1024;

    k_init<<<(n + 255) / 256, 256>>>(n);
    k_prep<<<(64 * 128 + 128 * 128 + 2 * 256 * 128 + 255) / 256, 256>>>(W1, W2, Wself, Wneigh);
    k_hist<<<(e + 255) / 256, 256>>>(er, e);
    k_scanA<<<nchunk, 256>>>(n);
    k_scanB<<<1, 256>>>(nchunk, n);
    k_scanC<<<nchunk, 256>>>(n);
    k_reorder<<<(e + 255) / 256, 256>>>(er, ec, ev, e);

    k_mlp_tc<<<ntile, 256, SMEM_MLP_TC>>>(mi, wi, ti, cont, memb, wemb, temb, b1, b2, h, n);

    // device pointers to g_wlh slices: pass via symbol-offset pointer
    __half* wlh_base = nullptr;
    cudaGetSymbolAddress((void**)&wlh_base, g_wlh);

    for (int l = 0; l < 2; l++) {
        int hw_blocks = (int)(((long long)n * 16 + 255) / 256);
        k_spmm<<<hw_blocks, 256>>>(n);
        k_layer_tc<<<ntile, 256, SMEM_TC>>>(wlh_base + (size_t)l * 256 * 128,
                                            bself + l * 128, bneigh + l * 128,
                                            h, n, l == 0 ? 1 : 0);
    }

    k_reduce<<<1024, 128>>>(h, n);
    k_final<<<1, 256>>>(out, n);
}

// round 6
// speedup vs baseline: 1.8485x; 1.0078x over previous
#include <cuda_runtime.h>
#include <cuda_fp16.h>

#define NMAX 200000
#define EMAX 6400000
#define HD 128

// ---------------- mma / ldmatrix helpers ------------------------------------
__device__ __forceinline__ unsigned smem_u32(const void* p) {
    return (unsigned)__cvta_generic_to_shared(p);
}
__device__ __forceinline__ void ldsm_x4(unsigned& r0, unsigned& r1, unsigned& r2, unsigned& r3,
                                        unsigned addr) {
    asm volatile("ldmatrix.sync.aligned.m8n8.x4.shared.b16 {%0,%1,%2,%3}, [%4];"
                 : "=r"(r0), "=r"(r1), "=r"(r2), "=r"(r3) : "r"(addr));
}
__device__ __forceinline__ void ldsm_x4_trans(unsigned& r0, unsigned& r1, unsigned& r2, unsigned& r3,
                                              unsigned addr) {
    asm volatile("ldmatrix.sync.aligned.m8n8.x4.trans.shared.b16 {%0,%1,%2,%3}, [%4];"
                 : "=r"(r0), "=r"(r1), "=r"(r2), "=r"(r3) : "r"(addr));
}
__device__ __forceinline__ void mma16816(float* d, unsigned a0, unsigned a1, unsigned a2, unsigned a3,
                                         unsigned b0, unsigned b1) {
    asm volatile("mma.sync.aligned.m16n8k16.row.col.f32.f16.f16.f32 "
                 "{%0,%1,%2,%3}, {%4,%5,%6,%7}, {%8,%9}, {%0,%1,%2,%3};"
                 : "+f"(d[0]), "+f"(d[1]), "+f"(d[2]), "+f"(d[3])
                 : "r"(a0), "r"(a1), "r"(a2), "r"(a3), "r"(b0), "r"(b1));
}

// ---------------- static device scratch (no allocations allowed) ------------
__device__ int g_cnt[NMAX];
__device__ int g_rowptr[NMAX + 1];
__device__ int g_cur[NMAX];
__device__ int g_part[256];
__device__ int g_partoff[256];
__device__ __align__(16) uint2 g_edges[EMAX];                 // (col, val-bits)
__device__ __align__(16) __half g_neighh[(size_t)NMAX * HD];  // fp16 neighbor agg
__device__ __align__(16) __half g_hb[(size_t)NMAX * HD];      // fp16 shadow of h
__device__ __align__(16) __half g_w1h[64 * 128];              // padded W1 fp16
__device__ __align__(16) __half g_w2h[128 * 128];
__device__ __align__(16) __half g_wlh[2 * 256 * 128];         // [l][Ws;Wn][128]
__device__ float g_gsum[HD];
__device__ unsigned g_gmax[HD];

// ---------------- weight fp16 pre-conversion --------------------------------
__global__ void k_prep(const float* __restrict__ W1, const float* __restrict__ W2,
                       const float* __restrict__ Wself, const float* __restrict__ Wneigh) {
    int i = blockIdx.x * blockDim.x + threadIdx.x;
    if (i < 64 * 128) {
        int r = i >> 7, c = i & 127;
        g_w1h[i] = __float2half(r < 60 ? W1[r * 128 + c] : 0.f);
    } else if (i < 64 * 128 + 128 * 128) {
        int j = i - 64 * 128;
        g_w2h[j] = __float2half(W2[j]);
    } else if (i < 64 * 128 + 128 * 128 + 2 * 256 * 128) {
        int j = i - 64 * 128 - 128 * 128;
        int l = j >> 15;
        int r = (j & 32767) >> 7;
        int c = j & 127;
        float v = (r < 128) ? Wself[l * 16384 + r * 128 + c]
                            : Wneigh[l * 16384 + (r - 128) * 128 + c];
        g_wlh[j] = __float2half(v);
    }
}

// ---------------- CSR build: histogram -> parallel scan -> reorder ----------
__global__ void k_hist(const int* __restrict__ er, int e) {
    int i = blockIdx.x * blockDim.x + threadIdx.x;
    int i4 = i * 4;
    if (i4 + 3 < e) {
        int4 r = *(const int4*)&er[i4];
        atomicAdd(&g_cnt[r.x], 1);
        atomicAdd(&g_cnt[r.y], 1);
        atomicAdd(&g_cnt[r.z], 1);
        atomicAdd(&g_cnt[r.w], 1);
    } else {
        for (int j = i4; j < e; j++) atomicAdd(&g_cnt[er[j]], 1);
    }
}

__global__ void k_scanA(int n) {  // per-1024-chunk sums
    __shared__ int s[256];
    int b = blockIdx.x, t = threadIdx.x;
    int i0 = b * 1024 + t * 4;
    int sum = 0;
    #pragma unroll
    for (int j = 0; j < 4; j++) { int i = i0 + j; if (i < n) sum += g_cnt[i]; }
    s[t] = sum;
    __syncthreads();
    for (int off = 128; off > 0; off >>= 1) {
        if (t < off) s[t] += s[t + off];
        __syncthreads();
    }
    if (t == 0) g_part[b] = s[0];
}

__global__ void k_scanB(int nb, int n) {  // scan partials (nb <= 256) + zero pool accs
    __shared__ int s[256];
    int t = threadIdx.x;
    if (t < HD) { g_gsum[t] = 0.f; g_gmax[t] = 0u; }
    int v = (t < nb) ? g_part[t] : 0;
    s[t] = v;
    __syncthreads();
    for (int off = 1; off < 256; off <<= 1) {
        int u = (t >= off) ? s[t - off] : 0;
        __syncthreads();
        s[t] += u;
        __syncthreads();
    }
    if (t < nb) g_partoff[t] = s[t] - v;
    if (t == 255) g_rowptr[n] = s[255];
}

__global__ void k_scanC(int n) {  // final exclusive scan + write
    __shared__ int s[256];
    int b = blockIdx.x, t = threadIdx.x;
    int i0 = b * 1024 + t * 4;
    int c[4]; int sum = 0;
    #pragma unroll
    for (int j = 0; j < 4; j++) { int i = i0 + j; c[j] = (i < n) ? g_cnt[i] : 0; sum += c[j]; }
    s[t] = sum;
    __syncthreads();
    for (int off = 1; off < 256; off <<= 1) {
        int u = (t >= off) ? s[t - off] : 0;
        __syncthreads();
        s[t] += u;
        __syncthreads();
    }
    int pre = g_partoff[b] + s[t] - sum;
    #pragma unroll
    for (int j = 0; j < 4; j++) {
        int i = i0 + j;
        if (i < n) { g_rowptr[i] = pre; g_cur[i] = pre; pre += c[j]; }
    }
}

__global__ void k_reorder(const int* __restrict__ er, const int* __restrict__ ec,
                          const float* __restrict__ ev, int e) {
    int i = blockIdx.x * blockDim.x + threadIdx.x;
    int i4 = i * 4;
    if (i4 + 3 < e) {
        int4 r = *(const int4*)&er[i4];
        int4 c = *(const int4*)&ec[i4];
        float4 v = *(const float4*)&ev[i4];
        int p0 = atomicAdd(&g_cur[r.x], 1);
        int p1 = atomicAdd(&g_cur[r.y], 1);
        int p2 = atomicAdd(&g_cur[r.z], 1);
        int p3 = atomicAdd(&g_cur[r.w], 1);
        g_edges[p0] = make_uint2((unsigned)c.x, __float_as_uint(v.x));
        g_edges[p1] = make_uint2((unsigned)c.y, __float_as_uint(v.y));
        g_edges[p2] = make_uint2((unsigned)c.z, __float_as_uint(v.z));
        g_edges[p3] = make_uint2((unsigned)c.w, __float_as_uint(v.w));
    } else {
        for (int j = i4; j < e; j++) {
            int p = atomicAdd(&g_cur[er[j]], 1);
            g_edges[p] = make_uint2((unsigned)ec[j], __float_as_uint(ev[j]));
        }
    }
}

// ---------------- tensor-core input MLP -------------------------------------
#define XSTR 72
#define WSTR 136
#define SMEM_MLP_TC ((128 * XSTR + 64 * WSTR + 128 * WSTR + 128 * WSTR) * 2)

__global__ void __launch_bounds__(256, 1) k_mlp_tc(
    const int* __restrict__ mi, const int* __restrict__ wi, const int* __restrict__ ti,
    const float* __restrict__ cont,
    const float* __restrict__ memb, const float* __restrict__ wemb, const float* __restrict__ temb,
    const float* __restrict__ b1, const float* __restrict__ b2,
    float* __restrict__ hout, int n)
{
    extern __shared__ __half smh[];
    __half* sX  = smh;                        // [128][72]
    __half* sW1 = sX + 128 * XSTR;            // [64][136]
    __half* sW2 = sW1 + 64 * WSTR;            // [128][136]
    __half* sH1 = sW2 + 128 * WSTR;           // [128][136]

    int tid = threadIdx.x;
    int base = blockIdx.x * 128;

    for (int i = tid; i < 64 * 16; i += 256) {
        int r = i >> 4, q = i & 15;
        *(uint4*)&sW1[r * WSTR + q * 8] = *(const uint4*)&g_w1h[i * 8];
    }
    for (int i = tid; i < 128 * 16; i += 256) {
        int r = i >> 4, q = i & 15;
        *(uint4*)&sW2[r * WSTR + q * 8] = *(const uint4*)&g_w2h[i * 8];
    }
    for (int i = tid; i < 128 * 64; i += 256) {
        int nd = i >> 6, f = i & 63;
        int node = base + nd;
        float v = 0.f;
        if (node < n && f < 60) {
            if (f < 16)       v = memb[mi[node] * 16 + f];
            else if (f < 32)  v = wemb[wi[node] * 16 + (f - 16)];
            else if (f < 48)  v = temb[ti[node] * 16 + (f - 32)];
            else              v = cont[(size_t)node * 12 + (f - 48)];
        }
        sX[nd * XSTR + f] = __float2half(v);
    }
    __syncthreads();

    int wid = tid >> 5;
    int lane = tid & 31;
    int m0 = wid * 16;
    int lg = lane >> 3, lr = lane & 7;
    int a_row = m0 + lr + (lg & 1) * 8;
    int a_colb = (lg >> 1) * 8;
    int b_rowb = lr + (lg & 1) * 8;
    int b_colb = (lg >> 1) * 8;
    int row0 = m0 + (lane >> 2);
    int cbase = (lane & 3) * 2;

    unsigned sX_b = smem_u32(sX);
    unsigned sW1_b = smem_u32(sW1);
    unsigned sW2_b = smem_u32(sW2);
    unsigned sH1_b = smem_u32(sH1);

    float acc[16][4];
    #pragma unroll
    for (int t = 0; t < 16; t++)
        #pragma unroll
        for (int c = 0; c < 4; c++) acc[t][c] = 0.f;

    #pragma unroll
    for (int ks = 0; ks < 4; ks++) {
        int k0 = ks * 16;
        unsigned a0, a1, a2, a3;
        ldsm_x4(a0, a1, a2, a3, sX_b + (unsigned)(a_row * XSTR + k0 + a_colb) * 2u);
        #pragma unroll
        for (int j = 0; j < 8; j++) {
            unsigned b0, b1r, b2r, b3;
            ldsm_x4_trans(b0, b1r, b2r, b3,
                          sW1_b + (unsigned)((k0 + b_rowb) * WSTR + j * 16 + b_colb) * 2u);
            mma16816(acc[2 * j], a0, a1, a2, a3, b0, b1r);
            mma16816(acc[2 * j + 1], a0, a1, a2, a3, b2r, b3);
        }
    }
    #pragma unroll
    for (int t = 0; t < 16; t++) {
        int col = t * 8 + cbase;
        float bb0 = b1[col], bb1 = b1[col + 1];
        __half2 h0 = __floats2half2_rn(fmaxf(acc[t][0] + bb0, 0.f), fmaxf(acc[t][1] + bb1, 0.f));
        __half2 h1v = __floats2half2_rn(fmaxf(acc[t][2] + bb0, 0.f), fmaxf(acc[t][3] + bb1, 0.f));
        *(__half2*)&sH1[row0 * WSTR + col] = h0;
        *(__half2*)&sH1[(row0 + 8) * WSTR + col] = h1v;
    }
    __syncthreads();

    #pragma unroll
    for (int t = 0; t < 16; t++)
        #pragma unroll
        for (int c = 0; c < 4; c++) acc[t][c] = 0.f;

    #pragma unroll 1
    for (int ks = 0; ks < 8; ks++) {
        int k0 = ks * 16;
        unsigned a0, a1, a2, a3;
        ldsm_x4(a0, a1, a2, a3, sH1_b + (unsigned)(a_row * WSTR + k0 + a_colb) * 2u);
        #pragma unroll
        for (int j = 0; j < 8; j++) {
            unsigned b0, b1r, b2r, b3;
            ldsm_x4_trans(b0, b1r, b2r, b3,
                          sW2_b + (unsigned)((k0 + b_rowb) * WSTR + j * 16 + b_colb) * 2u);
            mma16816(acc[2 * j], a0, a1, a2, a3, b0, b1r);
            mma16816(acc[2 * j + 1], a0, a1, a2, a3, b2r, b3);
        }
    }
    int node0 = base + row0;
    int node1 = node0 + 8;
    #pragma unroll
    for (int t = 0; t < 16; t++) {
        int col = t * 8 + cbase;
        float bb0 = b2[col], bb1 = b2[col + 1];
        if (node0 < n) {
            float x = fmaxf(acc[t][0] + bb0, 0.f);
            float y = fmaxf(acc[t][1] + bb1, 0.f);
            size_t off = (size_t)node0 * 128 + col;
            *(float2*)&hout[off] = make_float2(x, y);
            *(__half2*)&g_hb[off] = __floats2half2_rn(x, y);
        }
        if (node1 < n) {
            float x = fmaxf(acc[t][2] + bb0, 0.f);
            float y = fmaxf(acc[t][3] + bb1, 0.f);
            size_t off = (size_t)node1 * 128 + col;
            *(float2*)&hout[off] = make_float2(x, y);
            *(__half2*)&g_hb[off] = __floats2half2_rn(x, y);
        }
    }
}

// ---------------- SpMM: half-warp per row, streaming edges/out, L2 gathers --
__global__ void k_spmm(int n) {
    int row = (blockIdx.x * blockDim.x + threadIdx.x) >> 4;
    if (row >= n) return;
    int s = threadIdx.x & 15;
    int beg = g_rowptr[row], end = g_rowptr[row + 1];
    float acc0 = 0.f, acc1 = 0.f, acc2 = 0.f, acc3 = 0.f;
    float acc4 = 0.f, acc5 = 0.f, acc6 = 0.f, acc7 = 0.f;
    int e = beg;
    for (; e + 1 < end; e += 2) {
        uint2 e0 = __ldcs(&g_edges[e]);
        uint2 e1 = __ldcs(&g_edges[e + 1]);
        float v0 = __uint_as_float(e0.y);
        float v1 = __uint_as_float(e1.y);
        uint4 x0 = *(const uint4*)&g_hb[(size_t)e0.x * 128 + s * 8];
        uint4 x1 = *(const uint4*)&g_hb[(size_t)e1.x * 128 + s * 8];
        float2 p;
        p = __half22float2(*(__half2*)&x0.x); acc0 += v0 * p.x; acc1 += v0 * p.y;
        p = __half22float2(*(__half2*)&x0.y); acc2 += v0 * p.x; acc3 += v0 * p.y;
        p = __half22float2(*(__half2*)&x0.z); acc4 += v0 * p.x; acc5 += v0 * p.y;
        p = __half22float2(*(__half2*)&x0.w); acc6 += v0 * p.x; acc7 += v0 * p.y;
        p = __half22float2(*(__half2*)&x1.x); acc0 += v1 * p.x; acc1 += v1 * p.y;
        p = __half22float2(*(__half2*)&x1.y); acc2 += v1 * p.x; acc3 += v1 * p.y;
        p = __half22float2(*(__half2*)&x1.z); acc4 += v1 * p.x; acc5 += v1 * p.y;
        p = __half22float2(*(__half2*)&x1.w); acc6 += v1 * p.x; acc7 += v1 * p.y;
    }
    if (e < end) {
        uint2 e0 = __ldcs(&g_edges[e]);
        float v0 = __uint_as_float(e0.y);
        uint4 x0 = *(const uint4*)&g_hb[(size_t)e0.x * 128 + s * 8];
        float2 p;
        p = __half22float2(*(__half2*)&x0.x); acc0 += v0 * p.x; acc1 += v0 * p.y;
        p = __half22float2(*(__half2*)&x0.y); acc2 += v0 * p.x; acc3 += v0 * p.y;
        p = __half22float2(*(__half2*)&x0.z); acc4 += v0 * p.x; acc5 += v0 * p.y;
        p = __half22float2(*(__half2*)&x0.w); acc6 += v0 * p.x; acc7 += v0 * p.y;
    }
    uint4 o;
    __half2 h0 = __floats2half2_rn(acc0, acc1);
    __half2 h1 = __floats2half2_rn(acc2, acc3);
    __half2 h2 = __floats2half2_rn(acc4, acc5);
    __half2 h3 = __floats2half2_rn(acc6, acc7);
    o.x = *(unsigned*)&h0; o.y = *(unsigned*)&h1;
    o.z = *(unsigned*)&h2; o.w = *(unsigned*)&h3;
    __stcs((uint4*)&g_neighh[(size_t)row * 128 + s * 8], o);
}

// ---------------- tensor-core layer: h += relu([h;neigh]@[Ws;Wn] + b) -------
#define ASTR 264
#define SMEM_TC ((256 * WSTR + 128 * ASTR) * 2)

__global__ void __launch_bounds__(256, 1) k_layer_tc(
    const __half* __restrict__ wl, const float* __restrict__ bs, const float* __restrict__ bn,
    float* __restrict__ h, int n, int write_hb)
{
    extern __shared__ __half smh[];
    __half* sW = smh;                 // [256][136]
    __half* sA = smh + 256 * WSTR;    // [128][264]

    int tid = threadIdx.x;
    int base = blockIdx.x * 128;

    for (int i = tid; i < 256 * 16; i += 256) {
        int r = i >> 4, q = i & 15;
        *(uint4*)&sW[r * WSTR + q * 8] = *(const uint4*)&wl[i * 8];
    }
    for (int i = tid; i < 128 * 32; i += 256) {
        int nd = i >> 5, q = i & 31;
        int node = base + nd;
        uint4 v = {0u, 0u, 0u, 0u};
        if (node < n) {
            if (q < 16) v = *(const uint4*)&g_hb[(size_t)node * 128 + q * 8];
            else        v = *(const uint4*)&g_neighh[(size_t)node * 128 + (q - 16) * 8];
        }
        *(uint4*)&sA[nd * ASTR + q * 8] = v;
    }
    __syncthreads();

    int wid = tid >> 5;
    int lane = tid & 31;
    int m0 = wid * 16;
    int lg = lane >> 3, lr = lane & 7;
    int a_row = m0 + lr + (lg & 1) * 8;
    int a_colb = (lg >> 1) * 8;
    int b_rowb = lr + (lg & 1) * 8;
    int b_colb = (lg >> 1) * 8;

    unsigned sA_b = smem_u32(sA);
    unsigned sW_b = smem_u32(sW);

    float acc[16][4];
    #pragma unroll
    for (int t = 0; t < 16; t++)
        #pragma unroll
        for (int c = 0; c < 4; c++) acc[t][c] = 0.f;

    #pragma unroll 1
    for (int ks = 0; ks < 16; ks++) {
        int k0 = ks * 16;
        unsigned a0, a1, a2, a3;
        ldsm_x4(a0, a1, a2, a3, sA_b + (unsigned)(a_row * ASTR + k0 + a_colb) * 2u);
        #pragma unroll
        for (int j = 0; j < 8; j++) {
            unsigned b0, b1, b2, b3;
            ldsm_x4_trans(b0, b1, b2, b3,
                          sW_b + (unsigned)((k0 + b_rowb) * WSTR + j * 16 + b_colb) * 2u);
            mma16816(acc[2 * j], a0, a1, a2, a3, b0, b1);
            mma16816(acc[2 * j + 1], a0, a1, a2, a3, b2, b3);
        }
    }

    int row0 = m0 + (lane >> 2);
    int cbase = (lane & 3) * 2;
    int node0 = base + row0;
    int node1 = node0 + 8;
    #pragma unroll
    for (int t = 0; t < 16; t++) {
        int col = t * 8 + cbase;
        float bsum0 = bs[col] + bn[col];
        float bsum1 = bs[col + 1] + bn[col + 1];
        if (node0 < n) {
            size_t off = (size_t)node0 * 128 + col;
            float2* p = (float2*)&h[off];
            float2 hv = *p;
            hv.x += fmaxf(acc[t][0] + bsum0, 0.f);
            hv.y += fmaxf(acc[t][1] + bsum1, 0.f);
            *p = hv;
            if (write_hb) *(__half2*)&g_hb[off] = __floats2half2_rn(hv.x, hv.y);
        }
        if (node1 < n) {
            size_t off = (size_t)node1 * 128 + col;
            float2* p = (float2*)&h[off];
            float2 hv = *p;
            hv.x += fmaxf(acc[t][2] + bsum0, 0.f);
            hv.y += fmaxf(acc[t][3] + bsum1, 0.f);
            *p = hv;
            if (write_hb) *(__half2*)&g_hb[off] = __floats2half2_rn(hv.x, hv.y);
        }
    }
}

// ---------------- global mean/max pool --------------------------------------
__global__ void k_reduce(const float* __restrict__ h, int n) {
    int t = threadIdx.x;  // 128
    float s = 0.f, m = 0.f;
    for (int node = blockIdx.x; node < n; node += gridDim.x) {
        float v = __ldcs(&h[(size_t)node * 128 + t]);
        s += v;
        m = fmaxf(m, v);
    }
    atomicAdd(&g_gsum[t], s);
    atomicMax(&g_gmax[t], __float_as_uint(m));
}

__global__ void k_final(float* __restrict__ out, int n) {
    int t = threadIdx.x;  // 256
    if (t < 128) out[t] = g_gsum[t] / (float)n;
    else out[t] = __uint_as_float(g_gmax[t - 128]);
}

// ---------------- launch -----------------------------------------------------
extern "C" void kernel_launch(void* const* d_in, const int* in_sizes, int n_in,
                              void* d_out, int out_size) {
    const int*   mi   = (const int*)d_in[0];
    const int*   wi   = (const int*)d_in[1];
    const int*   ti   = (const int*)d_in[2];
    const float* cont = (const float*)d_in[3];
    const int*   er   = (const int*)d_in[4];
    const int*   ec   = (const int*)d_in[5];
    const float* ev   = (const float*)d_in[6];
    const float* memb = (const float*)d_in[7];
    const float* wemb = (const float*)d_in[8];
    const float* temb = (const float*)d_in[9];
    const float* W1   = (const float*)d_in[10];
    const float* b1   = (const float*)d_in[11];
    const float* W2   = (const float*)d_in[12];
    const float* b2   = (const float*)d_in[13];
    const float* Wself  = (const float*)d_in[14];
    const float* bself  = (const float*)d_in[15];
    const float* Wneigh = (const float*)d_in[16];
    const float* bneigh = (const float*)d_in[17];

    int n = in_sizes[0];
    int e = in_sizes[4];

    float* out = (float*)d_out;
    float* h = out + 256;

    cudaFuncSetAttribute(k_mlp_tc, cudaFuncAttributeMaxDynamicSharedMemorySize, SMEM_MLP_TC);
    cudaFuncSetAttribute(k_layer_tc, cudaFuncAttributeMaxDynamicSharedMemorySize, SMEM_TC);

    int ntile = (n + 127) / 128;
    int nchunk = (n + 1023) / 1024;

    void* cnt_ptr = nullptr;
    cudaGetSymbolAddress(&cnt_ptr, g_cnt);
    __half* wlh_base = nullptr;
    cudaGetSymbolAddress((void**)&wlh_base, g_wlh);

    cudaMemsetAsync(cnt_ptr, 0, (size_t)n * sizeof(int));
    k_prep<<<(64 * 128 + 128 * 128 + 2 * 256 * 128 + 255) / 256, 256>>>(W1, W2, Wself, Wneigh);
    k_hist<<<(e / 4 + 255) / 256, 256>>>(er, e);
    k_scanA<<<nchunk, 256>>>(n);
    k_scanB<<<1, 256>>>(nchunk, n);
    k_scanC<<<nchunk, 256>>>(n);
    k_reorder<<<(e / 4 + 255) / 256, 256>>>(er, ec, ev, e);

    k_mlp_tc<<<ntile, 256, SMEM_MLP_TC>>>(mi, wi, ti, cont, memb, wemb, temb, b1, b2, h, n);

    for (int l = 0; l < 2; l++) {
        int hw_blocks = (int)(((long long)n * 16 + 255) / 256);
        k_spmm<<<hw_blocks, 256>>>(n);
        k_layer_tc<<<ntile, 256, SMEM_TC>>>(wlh_base + (size_t)l * 256 * 128,
                                            bself + l * 128, bneigh + l * 128,
                                            h, n, l == 0 ? 1 : 0);
    }

    k_reduce<<<1024, 128>>>(h, n);
    k_final<<<1, 256>>>(out, n);
}